// round 1
// baseline (speedup 1.0000x reference)
#include <cuda_runtime.h>
#include <math.h>

#define BATCH 2
#define SEQ   768
#define DIM   768
#define NH    8
#define HD    96
#define BH    (BATCH*NH)          // 16
#define ROWS  (BATCH*SEQ)         // 1536
#define NOUT  (BATCH*SEQ*DIM)     // 1179648
#define NPROB (BATCH*NH*SEQ*SEQ)  // 9437184
#define LNEPS 1e-5f

// ---------------- device scratch (no allocations allowed) ----------------
__device__ float g_Q[NOUT];
__device__ float g_K[NOUT];
__device__ float g_V[NOUT];
__device__ float g_ctx[NOUT];
__device__ float g_att[NOUT];
__device__ float g_cd[BH*SEQ];   // q . Wd
__device__ float g_ca[BH*SEQ];   // q . Wa
__device__ float g_c0[BH*SEQ];   // q . (bd+ba)

// ---------------- reduction helpers ----------------
__device__ __forceinline__ float warp_sum(float v) {
    #pragma unroll
    for (int o = 16; o; o >>= 1) v += __shfl_xor_sync(0xffffffffu, v, o);
    return v;
}
__device__ __forceinline__ float warp_max(float v) {
    #pragma unroll
    for (int o = 16; o; o >>= 1) v = fmaxf(v, __shfl_xor_sync(0xffffffffu, v, o));
    return v;
}

// ---------------- generic NT GEMM: C = A[M,K] * B[N,K]^T + bias[n] ----------------
// M,N multiples of 64, K multiple of 16. 64x64 tile, 4x4 per thread.
__global__ void __launch_bounds__(256) gemm_nt_bias(
    const float* __restrict__ A, const float* __restrict__ Bm,
    const float* __restrict__ bias, float* __restrict__ C,
    int K, int lda, int ldb, int ldc)
{
    __shared__ float As[16][68];
    __shared__ float Bs[16][68];
    const int tid = threadIdx.x;
    const int tx = tid & 15, ty = tid >> 4;
    const int m0 = blockIdx.y << 6, n0 = blockIdx.x << 6;
    const int lr = tid >> 2;          // 0..63
    const int lc = (tid & 3) << 2;    // 0,4,8,12
    float acc[4][4] = {};

    for (int k0 = 0; k0 < K; k0 += 16) {
        float4 av = *(const float4*)(A  + (size_t)(m0 + lr) * lda + k0 + lc);
        float4 bv = *(const float4*)(Bm + (size_t)(n0 + lr) * ldb + k0 + lc);
        As[lc+0][lr]=av.x; As[lc+1][lr]=av.y; As[lc+2][lr]=av.z; As[lc+3][lr]=av.w;
        Bs[lc+0][lr]=bv.x; Bs[lc+1][lr]=bv.y; Bs[lc+2][lr]=bv.z; Bs[lc+3][lr]=bv.w;
        __syncthreads();
        #pragma unroll
        for (int k = 0; k < 16; ++k) {
            float4 a = *(const float4*)&As[k][ty << 2];
            float4 b = *(const float4*)&Bs[k][tx << 2];
            float af[4] = {a.x, a.y, a.z, a.w};
            float bf[4] = {b.x, b.y, b.z, b.w};
            #pragma unroll
            for (int i = 0; i < 4; ++i)
                #pragma unroll
                for (int j = 0; j < 4; ++j)
                    acc[i][j] += af[i] * bf[j];
        }
        __syncthreads();
    }
    #pragma unroll
    for (int i = 0; i < 4; ++i) {
        int m = m0 + (ty << 2) + i;
        #pragma unroll
        for (int j = 0; j < 4; ++j) {
            int n = n0 + (tx << 2) + j;
            C[(size_t)m * ldc + n] = acc[i][j] + bias[n];
        }
    }
}

// ---------------- per-(b,h,i) rank-1 bias coefficients ----------------
__global__ void __launch_bounds__(128) qproj_kernel(
    const float* __restrict__ Wd, const float* __restrict__ bd,
    const float* __restrict__ Wa, const float* __restrict__ ba)
{
    int warp = (blockIdx.x * blockDim.x + threadIdx.x) >> 5;
    int lane = threadIdx.x & 31;
    if (warp >= BH * SEQ) return;
    int b = warp / (NH * SEQ);
    int h = (warp / SEQ) % NH;
    int i = warp % SEQ;
    const float* q = g_Q + ((size_t)b * SEQ + i) * DIM + h * HD;
    float sd = 0.f, sa = 0.f, s0 = 0.f;
    #pragma unroll
    for (int d = lane; d < HD; d += 32) {
        float qv = q[d];
        sd = fmaf(qv, Wd[d], sd);
        sa = fmaf(qv, Wa[d], sa);
        s0 = fmaf(qv, bd[d] + ba[d], s0);
    }
    sd = warp_sum(sd); sa = warp_sum(sa); s0 = warp_sum(s0);
    if (lane == 0) { g_cd[warp] = sd; g_ca[warp] = sa; g_c0[warp] = s0; }
}

// ---------------- scores: per-(b,h) Q.K^T with fused rank-1 bias epilogue ----------------
__global__ void __launch_bounds__(256) scores_kernel(
    const float* __restrict__ dist, const float* __restrict__ ang,
    const float* __restrict__ mask, float* __restrict__ P)
{
    const int bh = blockIdx.z, b = bh >> 3, h = bh & 7;
    const float* A  = g_Q + (size_t)b * SEQ * DIM + h * HD;
    const float* Bm = g_K + (size_t)b * SEQ * DIM + h * HD;

    __shared__ float As[16][68];
    __shared__ float Bs[16][68];
    const int tid = threadIdx.x;
    const int tx = tid & 15, ty = tid >> 4;
    const int m0 = blockIdx.y << 6, n0 = blockIdx.x << 6;
    const int lr = tid >> 2;
    const int lc = (tid & 3) << 2;
    float acc[4][4] = {};

    for (int k0 = 0; k0 < HD; k0 += 16) {
        float4 av = *(const float4*)(A  + (size_t)(m0 + lr) * DIM + k0 + lc);
        float4 bv = *(const float4*)(Bm + (size_t)(n0 + lr) * DIM + k0 + lc);
        As[lc+0][lr]=av.x; As[lc+1][lr]=av.y; As[lc+2][lr]=av.z; As[lc+3][lr]=av.w;
        Bs[lc+0][lr]=bv.x; Bs[lc+1][lr]=bv.y; Bs[lc+2][lr]=bv.z; Bs[lc+3][lr]=bv.w;
        __syncthreads();
        #pragma unroll
        for (int k = 0; k < 16; ++k) {
            float4 a = *(const float4*)&As[k][ty << 2];
            float4 b4 = *(const float4*)&Bs[k][tx << 2];
            float af[4] = {a.x, a.y, a.z, a.w};
            float bf[4] = {b4.x, b4.y, b4.z, b4.w};
            #pragma unroll
            for (int i = 0; i < 4; ++i)
                #pragma unroll
                for (int j = 0; j < 4; ++j)
                    acc[i][j] += af[i] * bf[j];
        }
        __syncthreads();
    }

    const float inv = 0.1020620726159657f;  // 1/sqrt(96)
    #pragma unroll
    for (int i = 0; i < 4; ++i) {
        int m = m0 + (ty << 2) + i;
        float cdv = g_cd[bh * SEQ + m];
        float cav = g_ca[bh * SEQ + m];
        float c0v = g_c0[bh * SEQ + m];
        #pragma unroll
        for (int j = 0; j < 4; ++j) {
            int n = n0 + (tx << 2) + j;
            float dv = dist[((size_t)b * SEQ + m) * SEQ + n];
            float av = ang [((size_t)b * SEQ + m) * SEQ + n];
            float mb = (1.0f - mask[b * SEQ + n]) * -10000.0f;
            float s = acc[i][j] * inv;
            s = fmaf(dv, cdv, s);
            s = fmaf(av, cav, s);
            P[((size_t)bh * SEQ + m) * SEQ + n] = s + c0v + mb;
        }
    }
}

// ---------------- row softmax over 768 (in place) ----------------
__global__ void __launch_bounds__(256) softmax_kernel(float* __restrict__ P)
{
    __shared__ float shm[8];
    __shared__ float shs[8];
    float* p = P + (size_t)blockIdx.x * SEQ;
    const int tid = threadIdx.x;
    float v0 = p[tid], v1 = p[tid + 256], v2 = p[tid + 512];

    float mx = fmaxf(v0, fmaxf(v1, v2));
    mx = warp_max(mx);
    if ((tid & 31) == 0) shm[tid >> 5] = mx;
    __syncthreads();
    float t = (tid & 31) < 8 ? shm[tid & 31] : -1e30f;
    mx = warp_max(t);

    v0 = __expf(v0 - mx); v1 = __expf(v1 - mx); v2 = __expf(v2 - mx);
    float s = v0 + v1 + v2;
    s = warp_sum(s);
    if ((tid & 31) == 0) shs[tid >> 5] = s;
    __syncthreads();
    t = (tid & 31) < 8 ? shs[tid & 31] : 0.f;
    s = warp_sum(t);

    float r = 1.0f / s;
    p[tid] = v0 * r; p[tid + 256] = v1 * r; p[tid + 512] = v2 * r;
}

// ---------------- ctx = probs @ V (per b,h; N=96) ----------------
__global__ void __launch_bounds__(256) ctx_kernel(const float* __restrict__ P)
{
    const int bh = blockIdx.z, b = bh >> 3, h = bh & 7;
    const float* Pp = P + (size_t)bh * SEQ * SEQ;
    const float* Vp = g_V + (size_t)b * SEQ * DIM + h * HD;
    float* Cp = g_ctx + (size_t)b * SEQ * DIM + h * HD;
    const int m0 = blockIdx.y << 6;

    __shared__ float Ps[16][68];
    __shared__ float Vs[16][100];
    const int tid = threadIdx.x;
    const int tx = tid & 15, ty = tid >> 4;
    const int lr = tid >> 2;
    const int lc = (tid & 3) << 2;
    float acc[4][6] = {};

    for (int k0 = 0; k0 < SEQ; k0 += 16) {
        float4 pv = *(const float4*)(Pp + (size_t)(m0 + lr) * SEQ + k0 + lc);
        Ps[lc+0][lr]=pv.x; Ps[lc+1][lr]=pv.y; Ps[lc+2][lr]=pv.z; Ps[lc+3][lr]=pv.w;
        #pragma unroll
        for (int tgt = 0; tgt < 6; ++tgt) {
            int l = tid + tgt * 256;
            int kk = l / HD, nn = l - kk * HD;
            Vs[kk][nn] = Vp[(size_t)(k0 + kk) * DIM + nn];
        }
        __syncthreads();
        #pragma unroll
        for (int k = 0; k < 16; ++k) {
            float4 a = *(const float4*)&Ps[k][ty << 2];
            float af[4] = {a.x, a.y, a.z, a.w};
            float bf[6];
            #pragma unroll
            for (int j = 0; j < 6; ++j) bf[j] = Vs[k][tx * 6 + j];
            #pragma unroll
            for (int i = 0; i < 4; ++i)
                #pragma unroll
                for (int j = 0; j < 6; ++j)
                    acc[i][j] += af[i] * bf[j];
        }
        __syncthreads();
    }
    #pragma unroll
    for (int i = 0; i < 4; ++i) {
        int m = m0 + (ty << 2) + i;
        #pragma unroll
        for (int j = 0; j < 6; ++j)
            Cp[(size_t)m * DIM + tx * 6 + j] = acc[i][j];
    }
}

// ---------------- residual + layernorm ----------------
__global__ void __launch_bounds__(256) ln_kernel(
    const float* __restrict__ hs, const float* __restrict__ lng,
    const float* __restrict__ lnb, float* __restrict__ out)
{
    __shared__ float sh1[8];
    __shared__ float sh2[8];
    const int row = blockIdx.x;
    const float* a  = g_att + (size_t)row * DIM;
    const float* x0 = hs    + (size_t)row * DIM;
    const int tid = threadIdx.x;

    float x[3];
    float s = 0.f, s2 = 0.f;
    #pragma unroll
    for (int j = 0; j < 3; ++j) {
        int c = tid + j * 256;
        x[j] = a[c] + x0[c];
        s += x[j];
        s2 = fmaf(x[j], x[j], s2);
    }
    s = warp_sum(s); s2 = warp_sum(s2);
    if ((tid & 31) == 0) { sh1[tid >> 5] = s; sh2[tid >> 5] = s2; }
    __syncthreads();
    float t1 = (tid & 31) < 8 ? sh1[tid & 31] : 0.f;
    float t2 = (tid & 31) < 8 ? sh2[tid & 31] : 0.f;
    s = warp_sum(t1); s2 = warp_sum(t2);

    const float mu = s * (1.0f / DIM);
    const float var = s2 * (1.0f / DIM) - mu * mu;
    const float rs = rsqrtf(var + LNEPS);
    #pragma unroll
    for (int j = 0; j < 3; ++j) {
        int c = tid + j * 256;
        out[(size_t)row * DIM + c] = (x[j] - mu) * rs * lng[c] + lnb[c];
    }
}

// ---------------- launcher ----------------
extern "C" void kernel_launch(void* const* d_in, const int* in_sizes, int n_in,
                              void* d_out, int out_size)
{
    const float* hs   = (const float*)d_in[0];
    const float* dist = (const float*)d_in[1];
    const float* ang  = (const float*)d_in[2];
    const float* mask = (const float*)d_in[3];
    const float* Wq   = (const float*)d_in[4];
    const float* bq   = (const float*)d_in[5];
    const float* Wk   = (const float*)d_in[6];
    const float* bk   = (const float*)d_in[7];
    const float* Wv   = (const float*)d_in[8];
    const float* bv   = (const float*)d_in[9];
    const float* Wd   = (const float*)d_in[10];
    const float* bd   = (const float*)d_in[11];
    const float* Wa   = (const float*)d_in[12];
    const float* ba   = (const float*)d_in[13];
    const float* Wo   = (const float*)d_in[14];
    const float* bo   = (const float*)d_in[15];
    const float* lng  = (const float*)d_in[16];
    const float* lnb  = (const float*)d_in[17];

    float* out   = (float*)d_out;
    float* probs = out + NOUT;

    float *Qp, *Kp, *Vp, *Cp, *Ap;
    cudaGetSymbolAddress((void**)&Qp, g_Q);
    cudaGetSymbolAddress((void**)&Kp, g_K);
    cudaGetSymbolAddress((void**)&Vp, g_V);
    cudaGetSymbolAddress((void**)&Cp, g_ctx);
    cudaGetSymbolAddress((void**)&Ap, g_att);

    dim3 blk(256);
    dim3 gQKV(DIM / 64, ROWS / 64);        // 12 x 24

    gemm_nt_bias<<<gQKV, blk>>>(hs, Wq, bq, Qp, DIM, DIM, DIM, DIM);
    gemm_nt_bias<<<gQKV, blk>>>(hs, Wk, bk, Kp, DIM, DIM, DIM, DIM);
    gemm_nt_bias<<<gQKV, blk>>>(hs, Wv, bv, Vp, DIM, DIM, DIM, DIM);

    qproj_kernel<<<(BH * SEQ) / 4, 128>>>(Wd, bd, Wa, ba);

    scores_kernel<<<dim3(SEQ / 64, SEQ / 64, BH), blk>>>(dist, ang, mask, probs);
    softmax_kernel<<<BH * SEQ, 256>>>(probs);
    ctx_kernel<<<dim3(1, SEQ / 64, BH), blk>>>(probs);

    gemm_nt_bias<<<gQKV, blk>>>(Cp, Wo, bo, Ap, DIM, DIM, DIM, DIM);
    ln_kernel<<<ROWS, 256>>>(hs, lng, lnb, out);
}

// round 3
// speedup vs baseline: 2.0302x; 2.0302x over previous
#include <cuda_runtime.h>
#include <cuda_bf16.h>
#include <math.h>
#include <cstdint>

#define BATCH 2
#define SEQ   768
#define DIM   768
#define NH    8
#define HD    96
#define BH    (BATCH*NH)          // 16
#define ROWS  (BATCH*SEQ)         // 1536
#define NOUT  (BATCH*SEQ*DIM)     // 1179648
#define NPROB (BATCH*NH*SEQ*SEQ)  // 9437184
#define WSZ   (DIM*DIM)           // 589824
#define KEXT  (3*DIM)             // 2304
#define KS3   (3*HD)              // 288
#define LNEPS 1e-5f

// ---------------- device scratch ----------------
__device__ __align__(256) float g_Q[NOUT];
__device__ __align__(256) float g_K[NOUT];
__device__ __align__(256) float g_V[NOUT];
__device__ __align__(256) float g_ctx[NOUT];
__device__ __align__(256) float g_att[NOUT];
__device__ float g_cd[BH*SEQ];
__device__ float g_ca[BH*SEQ];
__device__ float g_c0[BH*SEQ];
__device__ __align__(256) __nv_bfloat16 g_Aext[ROWS*KEXT];     // [Ah|Al|Ah] of hs
__device__ __align__(256) __nv_bfloat16 g_Wext[2*DIM*KEXT];    // Wq,Wk [Bh|Bh|Bl]
__device__ __align__(256) __nv_bfloat16 g_Wvh[WSZ];
__device__ __align__(256) __nv_bfloat16 g_Woh[WSZ];
__device__ __align__(256) __nv_bfloat16 g_ctxh[NOUT];
__device__ __align__(256) __nv_bfloat16 g_Qs[BH*SEQ*KS3];      // per-head [h|l|h]
__device__ __align__(256) __nv_bfloat16 g_Ks[BH*SEQ*KS3];      // per-head [h|h|l]
__device__ __align__(256) __nv_bfloat16 g_Pb[NPROB];
__device__ __align__(256) __nv_bfloat16 g_Vt[BH*128*SEQ];      // padded to 128 rows

// ---------------- mma helpers (baseline sm80+ ISA, OK on sm_103) ----------------
__device__ __forceinline__ uint32_t smem_u32(const void* p) {
    uint32_t a;
    asm("{ .reg .u64 t; cvta.to.shared.u64 t, %1; cvt.u32.u64 %0, t; }" : "=r"(a) : "l"(p));
    return a;
}
__device__ __forceinline__ void ldm4(uint32_t r[4], uint32_t a) {
    asm volatile("ldmatrix.sync.aligned.m8n8.x4.shared.b16 {%0,%1,%2,%3}, [%4];"
        : "=r"(r[0]), "=r"(r[1]), "=r"(r[2]), "=r"(r[3]) : "r"(a));
}
__device__ __forceinline__ void ldm2(uint32_t r[2], uint32_t a) {
    asm volatile("ldmatrix.sync.aligned.m8n8.x2.shared.b16 {%0,%1}, [%2];"
        : "=r"(r[0]), "=r"(r[1]) : "r"(a));
}
__device__ __forceinline__ void mma16816(float c[4], const uint32_t a[4], const uint32_t b[2]) {
    asm volatile("mma.sync.aligned.m16n8k16.row.col.f32.bf16.bf16.f32 "
        "{%0,%1,%2,%3}, {%4,%5,%6,%7}, {%8,%9}, {%0,%1,%2,%3};"
        : "+f"(c[0]), "+f"(c[1]), "+f"(c[2]), "+f"(c[3])
        : "r"(a[0]), "r"(a[1]), "r"(a[2]), "r"(a[3]), "r"(b[0]), "r"(b[1]));
}
__device__ __forceinline__ void cp16(uint32_t dst, const void* src) {
    asm volatile("cp.async.cg.shared.global [%0], [%1], 16;" :: "r"(dst), "l"(src) : "memory");
}
__device__ __forceinline__ void cp_commit() { asm volatile("cp.async.commit_group;" ::: "memory"); }
template<int N> __device__ __forceinline__ void cp_wait() {
    asm volatile("cp.async.wait_group %0;" :: "n"(N) : "memory");
}

#define SST 40                               // smem row stride (bf16), padded
#define SMEM_BYTES (2*2*128*SST*2)           // 40960: 2 bufs x (A+B) x 128x40 bf16

// C[128x128] tile of A[M,K] * B[N,K]^T ; 8 warps (2m x 4n), warp tile 64x32.
__device__ __forceinline__ void gemm_tile(
    const __nv_bfloat16* __restrict__ A, int lda,
    const __nv_bfloat16* __restrict__ B, int ldb,
    int m0, int n0, int K, float acc[4][4][4], char* smem)
{
    __nv_bfloat16* As = (__nv_bfloat16*)smem;
    __nv_bfloat16* Bs = As + 2 * 128 * SST;
    const int tid = threadIdx.x;
    const int wid = tid >> 5, lane = tid & 31;
    const int wm = wid >> 2, wn = wid & 3;
    const uint32_t sA = smem_u32(As), sB = smem_u32(Bs);

    const int row = tid >> 2;     // 0..63
    const int jj  = tid & 3;      // 16B chunk within 32-wide k

    const int nch = K / 32;

    // prologue: chunk 0 -> buf 0
    {
        #pragma unroll
        for (int i = 0; i < 2; ++i) {
            int r = row + i * 64;
            cp16(sA + (r * SST + jj * 8) * 2, A + (size_t)(m0 + r) * lda + jj * 8);
            cp16(sB + (r * SST + jj * 8) * 2, B + (size_t)(n0 + r) * ldb + jj * 8);
        }
        cp_commit();
    }

    for (int c = 0; c < nch; ++c) {
        if (c + 1 < nch) {
            int k0 = (c + 1) * 32;
            uint32_t dA = sA + ((c + 1) & 1) * 128 * SST * 2;
            uint32_t dB = sB + ((c + 1) & 1) * 128 * SST * 2;
            #pragma unroll
            for (int i = 0; i < 2; ++i) {
                int r = row + i * 64;
                cp16(dA + (r * SST + jj * 8) * 2, A + (size_t)(m0 + r) * lda + k0 + jj * 8);
                cp16(dB + (r * SST + jj * 8) * 2, B + (size_t)(n0 + r) * ldb + k0 + jj * 8);
            }
            cp_commit();
            cp_wait<1>();
        } else {
            cp_wait<0>();
        }
        __syncthreads();

        uint32_t bA = sA + (c & 1) * 128 * SST * 2;
        uint32_t bB = sB + (c & 1) * 128 * SST * 2;
        #pragma unroll
        for (int ks = 0; ks < 2; ++ks) {
            const int k16 = ks * 16;
            uint32_t af[4][4], bfr[4][2];
            #pragma unroll
            for (int mf = 0; mf < 4; ++mf) {
                int baseRow = wm * 64 + mf * 16;
                int mi = lane >> 3, r = lane & 7;
                int rr = baseRow + (mi & 1) * 8 + r;
                int cc = k16 + (mi >> 1) * 8;
                ldm4(af[mf], bA + (rr * SST + cc) * 2);
            }
            #pragma unroll
            for (int nf = 0; nf < 4; ++nf) {
                int baseRow = wn * 32 + nf * 8;
                int r = lane & 7, mi = (lane >> 3) & 1;
                ldm2(bfr[nf], bB + ((baseRow + r) * SST + k16 + mi * 8) * 2);
            }
            #pragma unroll
            for (int mf = 0; mf < 4; ++mf)
                #pragma unroll
                for (int nf = 0; nf < 4; ++nf)
                    mma16816(acc[mf][nf], af[mf], bfr[nf]);
        }
        __syncthreads();
    }
}

// ---------------- projection GEMM (QK batched / V / out) ----------------
struct ProjArgs {
    const __nv_bfloat16* B[2];
    const float* bias[2];
    float* C[2];
};

__global__ void __launch_bounds__(256) gemm_proj(
    const __nv_bfloat16* __restrict__ A, int lda, int ldb, int K, ProjArgs args)
{
    __shared__ __align__(16) char smem[SMEM_BYTES];
    const int z = blockIdx.z;
    const int m0 = blockIdx.y << 7, n0 = blockIdx.x << 7;
    float acc[4][4][4] = {};
    gemm_tile(A, lda, args.B[z], ldb, m0, n0, K, acc, smem);

    const float* bias = args.bias[z];
    float* C = args.C[z];
    const int wid = threadIdx.x >> 5, lane = threadIdx.x & 31;
    const int wm = wid >> 2, wn = wid & 3;
    #pragma unroll
    for (int mf = 0; mf < 4; ++mf) {
        int r = m0 + wm * 64 + mf * 16 + (lane >> 2);
        #pragma unroll
        for (int nf = 0; nf < 4; ++nf) {
            int c = n0 + wn * 32 + nf * 8 + (lane & 3) * 2;
            float b0 = bias[c], b1 = bias[c + 1];
            float2 v0 = {acc[mf][nf][0] + b0, acc[mf][nf][1] + b1};
            float2 v1 = {acc[mf][nf][2] + b0, acc[mf][nf][3] + b1};
            *(float2*)(C + (size_t)r * DIM + c) = v0;
            *(float2*)(C + (size_t)(r + 8) * DIM + c) = v1;
        }
    }
}

// ---------------- scores GEMM + fused bias/mask epilogue ----------------
__global__ void __launch_bounds__(256) gemm_scores(
    const __nv_bfloat16* __restrict__ Qs, const __nv_bfloat16* __restrict__ Ks,
    const float* __restrict__ dist, const float* __restrict__ ang,
    const float* __restrict__ mask, float* __restrict__ P)
{
    __shared__ __align__(16) char smem[SMEM_BYTES];
    const int z = blockIdx.z, b = z >> 3;
    const __nv_bfloat16* A = Qs + (size_t)z * SEQ * KS3;
    const __nv_bfloat16* B = Ks + (size_t)z * SEQ * KS3;
    const int m0 = blockIdx.y << 7, n0 = blockIdx.x << 7;
    float acc[4][4][4] = {};
    gemm_tile(A, KS3, B, KS3, m0, n0, KS3, acc, smem);

    const int wid = threadIdx.x >> 5, lane = threadIdx.x & 31;
    const int wm = wid >> 2, wn = wid & 3;
    const float inv = 0.1020620726159657f;  // 1/sqrt(96)
    #pragma unroll
    for (int mf = 0; mf < 4; ++mf) {
        int r0 = m0 + wm * 64 + mf * 16 + (lane >> 2);
        #pragma unroll
        for (int half = 0; half < 2; ++half) {
            int r = r0 + half * 8;
            float cdv = g_cd[z * SEQ + r];
            float cav = g_ca[z * SEQ + r];
            float c0v = g_c0[z * SEQ + r];
            const float* drow = dist + ((size_t)b * SEQ + r) * SEQ;
            const float* arow = ang  + ((size_t)b * SEQ + r) * SEQ;
            float* prow = P + ((size_t)z * SEQ + r) * SEQ;
            #pragma unroll
            for (int nf = 0; nf < 4; ++nf) {
                int c = n0 + wn * 32 + nf * 8 + (lane & 3) * 2;
                float2 dv = *(const float2*)(drow + c);
                float2 av = *(const float2*)(arow + c);
                float2 mk = *(const float2*)(mask + b * SEQ + c);
                float s0 = acc[mf][nf][half * 2 + 0] * inv;
                float s1 = acc[mf][nf][half * 2 + 1] * inv;
                s0 = fmaf(dv.x, cdv, s0); s0 = fmaf(av.x, cav, s0);
                s1 = fmaf(dv.y, cdv, s1); s1 = fmaf(av.y, cav, s1);
                float2 o;
                o.x = s0 + c0v + (1.0f - mk.x) * -10000.0f;
                o.y = s1 + c0v + (1.0f - mk.y) * -10000.0f;
                *(float2*)(prow + c) = o;
            }
        }
    }
}

// ---------------- ctx = P @ V (NT vs transposed V, N padded to 128) ----------------
__global__ void __launch_bounds__(256) gemm_ctx(
    const __nv_bfloat16* __restrict__ Pb, const __nv_bfloat16* __restrict__ Vt)
{
    __shared__ __align__(16) char smem[SMEM_BYTES];
    const int z = blockIdx.z, b = z >> 3, h = z & 7;
    const __nv_bfloat16* A = Pb + (size_t)z * SEQ * SEQ;
    const __nv_bfloat16* B = Vt + (size_t)z * 128 * SEQ;
    const int m0 = blockIdx.y << 7;
    float acc[4][4][4] = {};
    gemm_tile(A, SEQ, B, SEQ, m0, 0, SEQ, acc, smem);

    const int wid = threadIdx.x >> 5, lane = threadIdx.x & 31;
    const int wm = wid >> 2, wn = wid & 3;
    if (wn == 3) return;   // cols 96..127 are padding
    #pragma unroll
    for (int mf = 0; mf < 4; ++mf) {
        int r = m0 + wm * 64 + mf * 16 + (lane >> 2);
        #pragma unroll
        for (int nf = 0; nf < 4; ++nf) {
            int c = wn * 32 + nf * 8 + (lane & 3) * 2;
            float2 v0 = {acc[mf][nf][0], acc[mf][nf][1]};
            float2 v1 = {acc[mf][nf][2], acc[mf][nf][3]};
            *(float2*)(g_ctx + ((size_t)b * SEQ + r) * DIM + h * HD + c) = v0;
            *(float2*)(g_ctx + ((size_t)b * SEQ + r + 8) * DIM + h * HD + c) = v1;
        }
    }
}

// ---------------- conversions ----------------
__global__ void __launch_bounds__(256) make_aext(const float* __restrict__ x,
                                                 __nv_bfloat16* __restrict__ dst)
{   // x [ROWS][768] -> dst [ROWS][2304] slabs [hi | lo | hi]
    int idx = blockIdx.x * 256 + threadIdx.x;
    int e = idx * 2;
    int r = e / DIM, c = e % DIM;
    float2 v = *(const float2*)(x + e);
    __nv_bfloat162 h, l;
    h.x = __float2bfloat16(v.x); l.x = __float2bfloat16(v.x - __bfloat162float(h.x));
    h.y = __float2bfloat16(v.y); l.y = __float2bfloat16(v.y - __bfloat162float(h.y));
    __nv_bfloat16* row = dst + (size_t)r * KEXT;
    *(__nv_bfloat162*)(row + c) = h;
    *(__nv_bfloat162*)(row + DIM + c) = l;
    *(__nv_bfloat162*)(row + 2 * DIM + c) = h;
}

__global__ void __launch_bounds__(256) make_bext(const float* __restrict__ w,
                                                 __nv_bfloat16* __restrict__ dst)
{   // w [768][768] -> dst [768][2304] slabs [hi | hi | lo]
    int idx = blockIdx.x * 256 + threadIdx.x;
    int e = idx * 2;
    int r = e / DIM, c = e % DIM;
    float2 v = *(const float2*)(w + e);
    __nv_bfloat162 h, l;
    h.x = __float2bfloat16(v.x); l.x = __float2bfloat16(v.x - __bfloat162float(h.x));
    h.y = __float2bfloat16(v.y); l.y = __float2bfloat16(v.y - __bfloat162float(h.y));
    __nv_bfloat16* row = dst + (size_t)r * KEXT;
    *(__nv_bfloat162*)(row + c) = h;
    *(__nv_bfloat162*)(row + DIM + c) = h;
    *(__nv_bfloat162*)(row + 2 * DIM + c) = l;
}

__global__ void __launch_bounds__(256) conv_hi(const float* __restrict__ x,
                                               __nv_bfloat16* __restrict__ y, int n)
{
    int i = (blockIdx.x * 256 + threadIdx.x) * 4;
    if (i >= n) return;
    float4 v = *(const float4*)(x + i);
    __nv_bfloat162 a, b;
    a.x = __float2bfloat16(v.x); a.y = __float2bfloat16(v.y);
    b.x = __float2bfloat16(v.z); b.y = __float2bfloat16(v.w);
    *(__nv_bfloat162*)(y + i) = a;
    *(__nv_bfloat162*)(y + i + 2) = b;
}

__global__ void __launch_bounds__(256) split_qk(const float* __restrict__ X,
                                                __nv_bfloat16* __restrict__ dst, int isQ)
{   // X [b][s][768] -> dst [(b*8+h)][s][288]:  Q: [h|l|h]  K: [h|h|l]
    int idx = blockIdx.x * 256 + threadIdx.x;     // per 2 d's
    int d = (idx % 48) * 2;
    int h = (idx / 48) & 7;
    int s = (idx / 384) % SEQ;
    int b = idx / 294912;
    float2 v = *(const float2*)(X + ((size_t)b * SEQ + s) * DIM + h * HD + d);
    __nv_bfloat162 hi, lo;
    hi.x = __float2bfloat16(v.x); lo.x = __float2bfloat16(v.x - __bfloat162float(hi.x));
    hi.y = __float2bfloat16(v.y); lo.y = __float2bfloat16(v.y - __bfloat162float(hi.y));
    __nv_bfloat16* row = dst + ((size_t)(b * NH + h) * SEQ + s) * KS3;
    if (isQ) {
        *(__nv_bfloat162*)(row + d) = hi;
        *(__nv_bfloat162*)(row + HD + d) = lo;
        *(__nv_bfloat162*)(row + 2 * HD + d) = hi;
    } else {
        *(__nv_bfloat162*)(row + d) = hi;
        *(__nv_bfloat162*)(row + HD + d) = hi;
        *(__nv_bfloat162*)(row + 2 * HD + d) = lo;
    }
}

__global__ void transpose_v(const float* __restrict__ V, __nv_bfloat16* __restrict__ Vt)
{   // grid (24, 4, 16), block (32, 8): V[b][s][h*96+d] -> Vt[bh][128][768], rows>=96 zero
    __shared__ float sm[32][33];
    const int bh = blockIdx.z, b = bh >> 3, h = bh & 7;
    const int s0 = blockIdx.x * 32, d0 = blockIdx.y * 32;
    const int tx = threadIdx.x, ty0 = threadIdx.y;
    #pragma unroll
    for (int k = 0; k < 4; ++k) {
        int ty = ty0 + k * 8;
        int dg = d0 + tx;
        float v = 0.f;
        if (dg < HD) v = V[((size_t)b * SEQ + s0 + ty) * DIM + h * HD + dg];
        sm[ty][tx] = v;
    }
    __syncthreads();
    #pragma unroll
    for (int k = 0; k < 4; ++k) {
        int ty = ty0 + k * 8;
        Vt[((size_t)bh * 128 + d0 + ty) * SEQ + s0 + tx] = __float2bfloat16(sm[tx][ty]);
    }
}

// ---------------- reductions ----------------
__device__ __forceinline__ float warp_sum(float v) {
    #pragma unroll
    for (int o = 16; o; o >>= 1) v += __shfl_xor_sync(0xffffffffu, v, o);
    return v;
}
__device__ __forceinline__ float warp_max(float v) {
    #pragma unroll
    for (int o = 16; o; o >>= 1) v = fmaxf(v, __shfl_xor_sync(0xffffffffu, v, o));
    return v;
}

// ---------------- rank-1 bias coefficients ----------------
__global__ void __launch_bounds__(128) qproj_kernel(
    const float* __restrict__ Wd, const float* __restrict__ bd,
    const float* __restrict__ Wa, const float* __restrict__ ba)
{
    int warp = (blockIdx.x * blockDim.x + threadIdx.x) >> 5;
    int lane = threadIdx.x & 31;
    if (warp >= BH * SEQ) return;
    int b = warp / (NH * SEQ);
    int h = (warp / SEQ) % NH;
    int i = warp % SEQ;
    const float* q = g_Q + ((size_t)b * SEQ + i) * DIM + h * HD;
    float sd = 0.f, sa = 0.f, s0 = 0.f;
    #pragma unroll
    for (int d = lane; d < HD; d += 32) {
        float qv = q[d];
        sd = fmaf(qv, Wd[d], sd);
        sa = fmaf(qv, Wa[d], sa);
        s0 = fmaf(qv, bd[d] + ba[d], s0);
    }
    sd = warp_sum(sd); sa = warp_sum(sa); s0 = warp_sum(s0);
    if (lane == 0) { g_cd[warp] = sd; g_ca[warp] = sa; g_c0[warp] = s0; }
}

// ---------------- softmax ----------------
__global__ void __launch_bounds__(256) softmax_kernel(float* __restrict__ P)
{
    __shared__ float shm[8];
    __shared__ float shs[8];
    float* p = P + (size_t)blockIdx.x * SEQ;
    const int tid = threadIdx.x;
    float v0 = p[tid], v1 = p[tid + 256], v2 = p[tid + 512];

    float mx = fmaxf(v0, fmaxf(v1, v2));
    mx = warp_max(mx);
    if ((tid & 31) == 0) shm[tid >> 5] = mx;
    __syncthreads();
    float t = (tid & 31) < 8 ? shm[tid & 31] : -1e30f;
    mx = warp_max(t);

    v0 = __expf(v0 - mx); v1 = __expf(v1 - mx); v2 = __expf(v2 - mx);
    float s = v0 + v1 + v2;
    s = warp_sum(s);
    if ((tid & 31) == 0) shs[tid >> 5] = s;
    __syncthreads();
    t = (tid & 31) < 8 ? shs[tid & 31] : 0.f;
    s = warp_sum(t);

    float r = 1.0f / s;
    p[tid] = v0 * r; p[tid + 256] = v1 * r; p[tid + 512] = v2 * r;
}

// ---------------- residual + layernorm ----------------
__global__ void __launch_bounds__(256) ln_kernel(
    const float* __restrict__ hs, const float* __restrict__ lng,
    const float* __restrict__ lnb, float* __restrict__ out)
{
    __shared__ float sh1[8];
    __shared__ float sh2[8];
    const int row = blockIdx.x;
    const float* a  = g_att + (size_t)row * DIM;
    const float* x0 = hs    + (size_t)row * DIM;
    const int tid = threadIdx.x;

    float x[3];
    float s = 0.f, s2 = 0.f;
    #pragma unroll
    for (int j = 0; j < 3; ++j) {
        int c = tid + j * 256;
        x[j] = a[c] + x0[c];
        s += x[j];
        s2 = fmaf(x[j], x[j], s2);
    }
    s = warp_sum(s); s2 = warp_sum(s2);
    if ((tid & 31) == 0) { sh1[tid >> 5] = s; sh2[tid >> 5] = s2; }
    __syncthreads();
    float t1 = (tid & 31) < 8 ? sh1[tid & 31] : 0.f;
    float t2 = (tid & 31) < 8 ? sh2[tid & 31] : 0.f;
    s = warp_sum(t1); s2 = warp_sum(t2);

    const float mu = s * (1.0f / DIM);
    const float var = s2 * (1.0f / DIM) - mu * mu;
    const float rs = rsqrtf(var + LNEPS);
    #pragma unroll
    for (int j = 0; j < 3; ++j) {
        int c = tid + j * 256;
        out[(size_t)row * DIM + c] = (x[j] - mu) * rs * lng[c] + lnb[c];
    }
}

// ---------------- launcher ----------------
extern "C" void kernel_launch(void* const* d_in, const int* in_sizes, int n_in,
                              void* d_out, int out_size)
{
    const float* hs   = (const float*)d_in[0];
    const float* dist = (const float*)d_in[1];
    const float* ang  = (const float*)d_in[2];
    const float* mask = (const float*)d_in[3];
    const float* Wq   = (const float*)d_in[4];
    const float* bq   = (const float*)d_in[5];
    const float* Wk   = (const float*)d_in[6];
    const float* bk   = (const float*)d_in[7];
    const float* Wv   = (const float*)d_in[8];
    const float* bv   = (const float*)d_in[9];
    const float* Wd   = (const float*)d_in[10];
    const float* bd   = (const float*)d_in[11];
    const float* Wa   = (const float*)d_in[12];
    const float* ba   = (const float*)d_in[13];
    const float* Wo   = (const float*)d_in[14];
    const float* bo   = (const float*)d_in[15];
    const float* lng  = (const float*)d_in[16];
    const float* lnb  = (const float*)d_in[17];

    float* out   = (float*)d_out;
    float* probs = out + NOUT;

    float *Qp, *Kp, *Vp, *Cp, *Ap;
    __nv_bfloat16 *Aext, *Wext, *Wvh, *Woh, *Ctxh, *Qs, *Ks, *Pb, *Vt;
    cudaGetSymbolAddress((void**)&Qp,   g_Q);
    cudaGetSymbolAddress((void**)&Kp,   g_K);
    cudaGetSymbolAddress((void**)&Vp,   g_V);
    cudaGetSymbolAddress((void**)&Cp,   g_ctx);
    cudaGetSymbolAddress((void**)&Ap,   g_att);
    cudaGetSymbolAddress((void**)&Aext, g_Aext);
    cudaGetSymbolAddress((void**)&Wext, g_Wext);
    cudaGetSymbolAddress((void**)&Wvh,  g_Wvh);
    cudaGetSymbolAddress((void**)&Woh,  g_Woh);
    cudaGetSymbolAddress((void**)&Ctxh, g_ctxh);
    cudaGetSymbolAddress((void**)&Qs,   g_Qs);
    cudaGetSymbolAddress((void**)&Ks,   g_Ks);
    cudaGetSymbolAddress((void**)&Pb,   g_Pb);
    cudaGetSymbolAddress((void**)&Vt,   g_Vt);

    // --- operand prep ---
    make_aext<<<NOUT/512, 256>>>(hs, Aext);
    make_bext<<<WSZ/512, 256>>>(Wq, Wext);
    make_bext<<<WSZ/512, 256>>>(Wk, Wext + (size_t)DIM * KEXT);
    conv_hi<<<WSZ/1024, 256>>>(Wv, Wvh, WSZ);
    conv_hi<<<WSZ/1024, 256>>>(Wo, Woh, WSZ);

    // --- Q,K projections (3-pass split, K=2304), batched over z ---
    ProjArgs qk;
    qk.B[0] = Wext;  qk.B[1] = Wext + (size_t)DIM * KEXT;
    qk.bias[0] = bq; qk.bias[1] = bk;
    qk.C[0] = Qp;    qk.C[1] = Kp;
    gemm_proj<<<dim3(DIM/128, ROWS/128, 2), 256>>>(Aext, KEXT, KEXT, KEXT, qk);

    // --- V projection (1-pass bf16): A = hi slab of Aext ---
    ProjArgs va;
    va.B[0] = Wvh; va.bias[0] = bv; va.C[0] = Vp;
    va.B[1] = Wvh; va.bias[1] = bv; va.C[1] = Vp;
    gemm_proj<<<dim3(DIM/128, ROWS/128, 1), 256>>>(Aext, KEXT, DIM, DIM, va);

    qproj_kernel<<<(BH * SEQ) / 4, 128>>>(Wd, bd, Wa, ba);

    // --- scores (3-pass split per head, K=288) ---
    split_qk<<<2304, 256>>>(Qp, Qs, 1);
    split_qk<<<2304, 256>>>(Kp, Ks, 0);
    gemm_scores<<<dim3(SEQ/128, SEQ/128, BH), 256>>>(Qs, Ks, dist, ang, mask, probs);

    softmax_kernel<<<BH * SEQ, 256>>>(probs);

    // --- ctx = P @ V (1-pass bf16) ---
    conv_hi<<<NPROB/1024, 256>>>(probs, Pb, NPROB);
    transpose_v<<<dim3(SEQ/32, 4, BH), dim3(32, 8)>>>(Vp, Vt);
    gemm_ctx<<<dim3(1, SEQ/128, BH), 256>>>(Pb, Vt);

    // --- out projection (1-pass bf16) ---
    conv_hi<<<NOUT/1024, 256>>>(Cp, Ctxh, NOUT);
    ProjArgs op;
    op.B[0] = Woh; op.bias[0] = bo; op.C[0] = Ap;
    op.B[1] = Woh; op.bias[1] = bo; op.C[1] = Ap;
    gemm_proj<<<dim3(DIM/128, ROWS/128, 1), 256>>>(Ctxh, DIM, DIM, DIM, op);

    ln_kernel<<<ROWS, 256>>>(hs, lng, lnb, out);
}

// round 4
// speedup vs baseline: 2.3593x; 1.1621x over previous
#include <cuda_runtime.h>
#include <cuda_bf16.h>
#include <math.h>
#include <cstdint>

#define BATCH 2
#define SEQ   768
#define DIM   768
#define NH    8
#define HD    96
#define BH    (BATCH*NH)          // 16
#define ROWS  (BATCH*SEQ)         // 1536
#define NOUT  (BATCH*SEQ*DIM)     // 1179648
#define NPROB (BATCH*NH*SEQ*SEQ)  // 9437184
#define WSZ   (DIM*DIM)           // 589824
#define KEXT  (3*DIM)             // 2304
#define KS3   (3*HD)              // 288
#define LNEPS 1e-5f

// ---------------- device scratch ----------------
__device__ __align__(256) float g_Q[NOUT];
__device__ __align__(256) float g_K[NOUT];
__device__ __align__(256) float g_att[NOUT];
__device__ float g_cd[BH*SEQ];
__device__ float g_ca[BH*SEQ];
__device__ float g_c0[BH*SEQ];
__device__ __align__(256) __nv_bfloat16 g_Aext[ROWS*KEXT];     // [Ah|Al|Ah] of hs
__device__ __align__(256) __nv_bfloat16 g_Wext[2*DIM*KEXT];    // Wq,Wk [Bh|Bh|Bl]
__device__ __align__(256) __nv_bfloat16 g_Wvh[WSZ];
__device__ __align__(256) __nv_bfloat16 g_Woh[WSZ];
__device__ __align__(256) __nv_bfloat16 g_ctxh[NOUT];
__device__ __align__(256) __nv_bfloat16 g_Qs[BH*SEQ*KS3];      // per-head [h|l|h]
__device__ __align__(256) __nv_bfloat16 g_Ks[BH*SEQ*KS3];      // per-head [h|h|l]
__device__ __align__(256) __nv_bfloat16 g_Pb[NPROB];
__device__ __align__(256) __nv_bfloat16 g_Vt[BATCH*DIM*SEQ + 32*SEQ]; // [b][d][s], 32-row guard

// ---------------- mma helpers (baseline sm80+ ISA) ----------------
__device__ __forceinline__ uint32_t smem_u32(const void* p) {
    uint32_t a;
    asm("{ .reg .u64 t; cvta.to.shared.u64 t, %1; cvt.u32.u64 %0, t; }" : "=r"(a) : "l"(p));
    return a;
}
__device__ __forceinline__ void ldm4(uint32_t r[4], uint32_t a) {
    asm volatile("ldmatrix.sync.aligned.m8n8.x4.shared.b16 {%0,%1,%2,%3}, [%4];"
        : "=r"(r[0]), "=r"(r[1]), "=r"(r[2]), "=r"(r[3]) : "r"(a));
}
__device__ __forceinline__ void ldm2(uint32_t r[2], uint32_t a) {
    asm volatile("ldmatrix.sync.aligned.m8n8.x2.shared.b16 {%0,%1}, [%2];"
        : "=r"(r[0]), "=r"(r[1]) : "r"(a));
}
__device__ __forceinline__ void mma16816(float c[4], const uint32_t a[4], const uint32_t b[2]) {
    asm volatile("mma.sync.aligned.m16n8k16.row.col.f32.bf16.bf16.f32 "
        "{%0,%1,%2,%3}, {%4,%5,%6,%7}, {%8,%9}, {%0,%1,%2,%3};"
        : "+f"(c[0]), "+f"(c[1]), "+f"(c[2]), "+f"(c[3])
        : "r"(a[0]), "r"(a[1]), "r"(a[2]), "r"(a[3]), "r"(b[0]), "r"(b[1]));
}
__device__ __forceinline__ void cp16(uint32_t dst, const void* src) {
    asm volatile("cp.async.cg.shared.global [%0], [%1], 16;" :: "r"(dst), "l"(src) : "memory");
}
__device__ __forceinline__ void cp_commit() { asm volatile("cp.async.commit_group;" ::: "memory"); }
template<int N> __device__ __forceinline__ void cp_wait() {
    asm volatile("cp.async.wait_group %0;" :: "n"(N) : "memory");
}

#define SST 40                               // smem row stride (bf16)
#define SMEM_BYTES (2*2*128*SST*2)           // 40960

// C[128x128] tile of A[M,K] * B[N,K]^T ; 8 warps (2m x 4n), warp tile 64x32.
__device__ __forceinline__ void gemm_tile(
    const __nv_bfloat16* __restrict__ A, int lda,
    const __nv_bfloat16* __restrict__ B, int ldb,
    int m0, int n0, int K, float acc[4][4][4], char* smem)
{
    __nv_bfloat16* As = (__nv_bfloat16*)smem;
    __nv_bfloat16* Bs = As + 2 * 128 * SST;
    const int tid = threadIdx.x;
    const int wid = tid >> 5, lane = tid & 31;
    const int wm = wid >> 2, wn = wid & 3;
    const uint32_t sA = smem_u32(As), sB = smem_u32(Bs);

    const int row = tid >> 2;     // 0..63
    const int jj  = tid & 3;      // 16B chunk within 32-wide k

    const int nch = K / 32;

    {
        #pragma unroll
        for (int i = 0; i < 2; ++i) {
            int r = row + i * 64;
            cp16(sA + (r * SST + jj * 8) * 2, A + (size_t)(m0 + r) * lda + jj * 8);
            cp16(sB + (r * SST + jj * 8) * 2, B + (size_t)(n0 + r) * ldb + jj * 8);
        }
        cp_commit();
    }

    for (int c = 0; c < nch; ++c) {
        if (c + 1 < nch) {
            int k0 = (c + 1) * 32;
            uint32_t dA = sA + ((c + 1) & 1) * 128 * SST * 2;
            uint32_t dB = sB + ((c + 1) & 1) * 128 * SST * 2;
            #pragma unroll
            for (int i = 0; i < 2; ++i) {
                int r = row + i * 64;
                cp16(dA + (r * SST + jj * 8) * 2, A + (size_t)(m0 + r) * lda + k0 + jj * 8);
                cp16(dB + (r * SST + jj * 8) * 2, B + (size_t)(n0 + r) * ldb + k0 + jj * 8);
            }
            cp_commit();
            cp_wait<1>();
        } else {
            cp_wait<0>();
        }
        __syncthreads();

        uint32_t bA = sA + (c & 1) * 128 * SST * 2;
        uint32_t bB = sB + (c & 1) * 128 * SST * 2;
        #pragma unroll
        for (int ks = 0; ks < 2; ++ks) {
            const int k16 = ks * 16;
            uint32_t af[4][4], bfr[4][2];
            #pragma unroll
            for (int mf = 0; mf < 4; ++mf) {
                int baseRow = wm * 64 + mf * 16;
                int mi = lane >> 3, r = lane & 7;
                int rr = baseRow + (mi & 1) * 8 + r;
                int cc = k16 + (mi >> 1) * 8;
                ldm4(af[mf], bA + (rr * SST + cc) * 2);
            }
            #pragma unroll
            for (int nf = 0; nf < 4; ++nf) {
                int baseRow = wn * 32 + nf * 8;
                int r = lane & 7, mi = (lane >> 3) & 1;
                ldm2(bfr[nf], bB + ((baseRow + r) * SST + k16 + mi * 8) * 2);
            }
            #pragma unroll
            for (int mf = 0; mf < 4; ++mf)
                #pragma unroll
                for (int nf = 0; nf < 4; ++nf)
                    mma16816(acc[mf][nf], af[mf], bfr[nf]);
        }
        __syncthreads();
    }
}

// ---------------- stage 1: Q-proj, K-proj (3-pass split) + Vt = Wv @ hs^T (bf16) ----------------
__global__ void __launch_bounds__(256) gemm_stage1(
    const float* __restrict__ bq, const float* __restrict__ bk,
    const float* __restrict__ bv)
{
    const int z = blockIdx.z;
    if (z >= 2 && blockIdx.y >= 6) return;   // Vt GEMM is M=768 (6 y-tiles)
    __shared__ __align__(16) char smem[SMEM_BYTES];
    const int m0 = blockIdx.y << 7, n0 = blockIdx.x << 7;
    const int wid = threadIdx.x >> 5, lane = threadIdx.x & 31;
    const int wm = wid >> 2, wn = wid & 3;
    float acc[4][4][4] = {};

    if (z < 2) {
        const __nv_bfloat16* B = g_Wext + (size_t)z * DIM * KEXT;
        gemm_tile(g_Aext, KEXT, B, KEXT, m0, n0, KEXT, acc, smem);
        const float* bias = z ? bk : bq;
        float* C = z ? g_K : g_Q;
        #pragma unroll
        for (int mf = 0; mf < 4; ++mf) {
            int r = m0 + wm * 64 + mf * 16 + (lane >> 2);
            #pragma unroll
            for (int nf = 0; nf < 4; ++nf) {
                int c = n0 + wn * 32 + nf * 8 + (lane & 3) * 2;
                float b0 = bias[c], b1 = bias[c + 1];
                float2 v0 = {acc[mf][nf][0] + b0, acc[mf][nf][1] + b1};
                float2 v1 = {acc[mf][nf][2] + b0, acc[mf][nf][3] + b1};
                *(float2*)(C + (size_t)r * DIM + c) = v0;
                *(float2*)(C + (size_t)(r + 8) * DIM + c) = v1;
            }
        }
    } else {
        const int b = z - 2;
        // Vt[b][d][s] = sum_k Wv[d][k]*hs[b][s][k] + bv[d]; A=Wv_hi, B=hs_hi slab
        const __nv_bfloat16* B = g_Aext + (size_t)b * SEQ * KEXT;
        gemm_tile(g_Wvh, DIM, B, KEXT, m0, n0, DIM, acc, smem);
        __nv_bfloat16* Vt = g_Vt + (size_t)b * DIM * SEQ;
        #pragma unroll
        for (int mf = 0; mf < 4; ++mf) {
            int r = m0 + wm * 64 + mf * 16 + (lane >> 2);
            float bv0 = bv[r], bv8 = bv[r + 8];
            #pragma unroll
            for (int nf = 0; nf < 4; ++nf) {
                int c = n0 + wn * 32 + nf * 8 + (lane & 3) * 2;
                __nv_bfloat162 h0, h1;
                h0.x = __float2bfloat16(acc[mf][nf][0] + bv0);
                h0.y = __float2bfloat16(acc[mf][nf][1] + bv0);
                h1.x = __float2bfloat16(acc[mf][nf][2] + bv8);
                h1.y = __float2bfloat16(acc[mf][nf][3] + bv8);
                *(__nv_bfloat162*)(Vt + (size_t)r * SEQ + c) = h0;
                *(__nv_bfloat162*)(Vt + (size_t)(r + 8) * SEQ + c) = h1;
            }
        }
    }
}

// ---------------- scores GEMM + fused bias/mask epilogue ----------------
__global__ void __launch_bounds__(256) gemm_scores(
    const float* __restrict__ dist, const float* __restrict__ ang,
    const float* __restrict__ mask, float* __restrict__ P)
{
    __shared__ __align__(16) char smem[SMEM_BYTES];
    const int z = blockIdx.z, b = z >> 3;
    const __nv_bfloat16* A = g_Qs + (size_t)z * SEQ * KS3;
    const __nv_bfloat16* B = g_Ks + (size_t)z * SEQ * KS3;
    const int m0 = blockIdx.y << 7, n0 = blockIdx.x << 7;
    float acc[4][4][4] = {};
    gemm_tile(A, KS3, B, KS3, m0, n0, KS3, acc, smem);

    const int wid = threadIdx.x >> 5, lane = threadIdx.x & 31;
    const int wm = wid >> 2, wn = wid & 3;
    const float inv = 0.1020620726159657f;  // 1/sqrt(96)
    #pragma unroll
    for (int mf = 0; mf < 4; ++mf) {
        int r0 = m0 + wm * 64 + mf * 16 + (lane >> 2);
        #pragma unroll
        for (int half = 0; half < 2; ++half) {
            int r = r0 + half * 8;
            float cdv = g_cd[z * SEQ + r];
            float cav = g_ca[z * SEQ + r];
            float c0v = g_c0[z * SEQ + r];
            const float* drow = dist + ((size_t)b * SEQ + r) * SEQ;
            const float* arow = ang  + ((size_t)b * SEQ + r) * SEQ;
            float* prow = P + ((size_t)z * SEQ + r) * SEQ;
            #pragma unroll
            for (int nf = 0; nf < 4; ++nf) {
                int c = n0 + wn * 32 + nf * 8 + (lane & 3) * 2;
                float2 dv = *(const float2*)(drow + c);
                float2 av = *(const float2*)(arow + c);
                float2 mk = *(const float2*)(mask + b * SEQ + c);
                float s0 = acc[mf][nf][half * 2 + 0] * inv;
                float s1 = acc[mf][nf][half * 2 + 1] * inv;
                s0 = fmaf(dv.x, cdv, s0); s0 = fmaf(av.x, cav, s0);
                s1 = fmaf(dv.y, cdv, s1); s1 = fmaf(av.y, cav, s1);
                float2 o;
                o.x = s0 + c0v + (1.0f - mk.x) * -10000.0f;
                o.y = s1 + c0v + (1.0f - mk.y) * -10000.0f;
                *(float2*)(prow + c) = o;
            }
        }
    }
}

// ---------------- ctx = P @ V^T slice; writes bf16 ctxh directly ----------------
__global__ void __launch_bounds__(256) gemm_ctx()
{
    __shared__ __align__(16) char smem[SMEM_BYTES];
    const int z = blockIdx.z, b = z >> 3, h = z & 7;
    const __nv_bfloat16* A = g_Pb + (size_t)z * SEQ * SEQ;
    const __nv_bfloat16* B = g_Vt + (size_t)b * DIM * SEQ;  // rows h*96..h*96+127 (guarded)
    const int m0 = blockIdx.y << 7;
    float acc[4][4][4] = {};
    gemm_tile(A, SEQ, B, SEQ, m0, h * HD, SEQ, acc, smem);

    const int wid = threadIdx.x >> 5, lane = threadIdx.x & 31;
    const int wm = wid >> 2, wn = wid & 3;
    if (wn == 3) return;   // cols 96..127 cross into next head: discard
    #pragma unroll
    for (int mf = 0; mf < 4; ++mf) {
        int r = m0 + wm * 64 + mf * 16 + (lane >> 2);
        #pragma unroll
        for (int nf = 0; nf < 4; ++nf) {
            int c = wn * 32 + nf * 8 + (lane & 3) * 2;
            __nv_bfloat162 h0, h1;
            h0.x = __float2bfloat16(acc[mf][nf][0]);
            h0.y = __float2bfloat16(acc[mf][nf][1]);
            h1.x = __float2bfloat16(acc[mf][nf][2]);
            h1.y = __float2bfloat16(acc[mf][nf][3]);
            *(__nv_bfloat162*)(g_ctxh + ((size_t)b * SEQ + r) * DIM + h * HD + c) = h0;
            *(__nv_bfloat162*)(g_ctxh + ((size_t)b * SEQ + r + 8) * DIM + h * HD + c) = h1;
        }
    }
}

// ---------------- out projection: att = ctxh @ Woh^T + bo ----------------
__global__ void __launch_bounds__(256) gemm_out(const float* __restrict__ bo)
{
    __shared__ __align__(16) char smem[SMEM_BYTES];
    const int m0 = blockIdx.y << 7, n0 = blockIdx.x << 7;
    float acc[4][4][4] = {};
    gemm_tile(g_ctxh, DIM, g_Woh, DIM, m0, n0, DIM, acc, smem);

    const int wid = threadIdx.x >> 5, lane = threadIdx.x & 31;
    const int wm = wid >> 2, wn = wid & 3;
    #pragma unroll
    for (int mf = 0; mf < 4; ++mf) {
        int r = m0 + wm * 64 + mf * 16 + (lane >> 2);
        #pragma unroll
        for (int nf = 0; nf < 4; ++nf) {
            int c = n0 + wn * 32 + nf * 8 + (lane & 3) * 2;
            float b0 = bo[c], b1 = bo[c + 1];
            float2 v0 = {acc[mf][nf][0] + b0, acc[mf][nf][1] + b1};
            float2 v1 = {acc[mf][nf][2] + b0, acc[mf][nf][3] + b1};
            *(float2*)(g_att + (size_t)r * DIM + c) = v0;
            *(float2*)(g_att + (size_t)(r + 8) * DIM + c) = v1;
        }
    }
}

// ---------------- batched operand prep ----------------
__global__ void __launch_bounds__(256) prep_all(
    const float* __restrict__ hs, const float* __restrict__ Wq,
    const float* __restrict__ Wk, const float* __restrict__ Wv,
    const float* __restrict__ Wo)
{
    const int z = blockIdx.y;
    const int idx = blockIdx.x * 256 + threadIdx.x;
    const int e = idx * 2;
    if (z == 0) {
        // hs -> Aext [hi | lo | hi]
        int r = e / DIM, c = e % DIM;
        float2 v = *(const float2*)(hs + e);
        __nv_bfloat162 h, l;
        h.x = __float2bfloat16(v.x); l.x = __float2bfloat16(v.x - __bfloat162float(h.x));
        h.y = __float2bfloat16(v.y); l.y = __float2bfloat16(v.y - __bfloat162float(h.y));
        __nv_bfloat16* row = g_Aext + (size_t)r * KEXT;
        *(__nv_bfloat162*)(row + c) = h;
        *(__nv_bfloat162*)(row + DIM + c) = l;
        *(__nv_bfloat162*)(row + 2 * DIM + c) = h;
        return;
    }
    if (e >= WSZ) return;
    if (z <= 2) {
        // Wq/Wk -> Wext [hi | hi | lo]
        const float* w = (z == 1) ? Wq : Wk;
        int r = e / DIM, c = e % DIM;
        float2 v = *(const float2*)(w + e);
        __nv_bfloat162 h, l;
        h.x = __float2bfloat16(v.x); l.x = __float2bfloat16(v.x - __bfloat162float(h.x));
        h.y = __float2bfloat16(v.y); l.y = __float2bfloat16(v.y - __bfloat162float(h.y));
        __nv_bfloat16* row = g_Wext + (size_t)(z - 1) * DIM * KEXT + (size_t)r * KEXT;
        *(__nv_bfloat162*)(row + c) = h;
        *(__nv_bfloat162*)(row + DIM + c) = h;
        *(__nv_bfloat162*)(row + 2 * DIM + c) = l;
    } else {
        const float* w = (z == 3) ? Wv : Wo;
        __nv_bfloat16* y = (z == 3) ? g_Wvh : g_Woh;
        float2 v = *(const float2*)(w + e);
        __nv_bfloat162 hh;
        hh.x = __float2bfloat16(v.x); hh.y = __float2bfloat16(v.y);
        *(__nv_bfloat162*)(y + e) = hh;
    }
}

// ---------------- split Q/K into per-head 3-slab bf16 ----------------
__global__ void __launch_bounds__(256) split_qk(void)
{
    const int isQ = (blockIdx.y == 0);
    const float* X = isQ ? g_Q : g_K;
    __nv_bfloat16* dst = isQ ? g_Qs : g_Ks;
    int idx = blockIdx.x * 256 + threadIdx.x;     // per 2 d's
    int d = (idx % 48) * 2;
    int h = (idx / 48) & 7;
    int s = (idx / 384) % SEQ;
    int b = idx / 294912;
    float2 v = *(const float2*)(X + ((size_t)b * SEQ + s) * DIM + h * HD + d);
    __nv_bfloat162 hi, lo;
    hi.x = __float2bfloat16(v.x); lo.x = __float2bfloat16(v.x - __bfloat162float(hi.x));
    hi.y = __float2bfloat16(v.y); lo.y = __float2bfloat16(v.y - __bfloat162float(hi.y));
    __nv_bfloat16* row = dst + ((size_t)(b * NH + h) * SEQ + s) * KS3;
    if (isQ) {
        *(__nv_bfloat162*)(row + d) = hi;
        *(__nv_bfloat162*)(row + HD + d) = lo;
        *(__nv_bfloat162*)(row + 2 * HD + d) = hi;
    } else {
        *(__nv_bfloat162*)(row + d) = hi;
        *(__nv_bfloat162*)(row + HD + d) = hi;
        *(__nv_bfloat162*)(row + 2 * HD + d) = lo;
    }
}

// ---------------- reductions ----------------
__device__ __forceinline__ float warp_sum(float v) {
    #pragma unroll
    for (int o = 16; o; o >>= 1) v += __shfl_xor_sync(0xffffffffu, v, o);
    return v;
}
__device__ __forceinline__ float warp_max(float v) {
    #pragma unroll
    for (int o = 16; o; o >>= 1) v = fmaxf(v, __shfl_xor_sync(0xffffffffu, v, o));
    return v;
}

// ---------------- rank-1 bias coefficients ----------------
__global__ void __launch_bounds__(128) qproj_kernel(
    const float* __restrict__ Wd, const float* __restrict__ bd,
    const float* __restrict__ Wa, const float* __restrict__ ba)
{
    int warp = (blockIdx.x * blockDim.x + threadIdx.x) >> 5;
    int lane = threadIdx.x & 31;
    if (warp >= BH * SEQ) return;
    int b = warp / (NH * SEQ);
    int h = (warp / SEQ) % NH;
    int i = warp % SEQ;
    const float* q = g_Q + ((size_t)b * SEQ + i) * DIM + h * HD;
    float sd = 0.f, sa = 0.f, s0 = 0.f;
    #pragma unroll
    for (int d = lane; d < HD; d += 32) {
        float qv = q[d];
        sd = fmaf(qv, Wd[d], sd);
        sa = fmaf(qv, Wa[d], sa);
        s0 = fmaf(qv, bd[d] + ba[d], s0);
    }
    sd = warp_sum(sd); sa = warp_sum(sa); s0 = warp_sum(s0);
    if (lane == 0) { g_cd[warp] = sd; g_ca[warp] = sa; g_c0[warp] = s0; }
}

// ---------------- softmax (fp32 in place + bf16 copy) ----------------
__global__ void __launch_bounds__(256) softmax_kernel(float* __restrict__ P)
{
    __shared__ float shm[8];
    __shared__ float shs[8];
    float* p = P + (size_t)blockIdx.x * SEQ;
    __nv_bfloat16* pb = g_Pb + (size_t)blockIdx.x * SEQ;
    const int tid = threadIdx.x;
    float v0 = p[tid], v1 = p[tid + 256], v2 = p[tid + 512];

    float mx = fmaxf(v0, fmaxf(v1, v2));
    mx = warp_max(mx);
    if ((tid & 31) == 0) shm[tid >> 5] = mx;
    __syncthreads();
    float t = (tid & 31) < 8 ? shm[tid & 31] : -1e30f;
    mx = warp_max(t);

    v0 = __expf(v0 - mx); v1 = __expf(v1 - mx); v2 = __expf(v2 - mx);
    float s = v0 + v1 + v2;
    s = warp_sum(s);
    if ((tid & 31) == 0) shs[tid >> 5] = s;
    __syncthreads();
    t = (tid & 31) < 8 ? shs[tid & 31] : 0.f;
    s = warp_sum(t);

    float r = 1.0f / s;
    float o0 = v0 * r, o1 = v1 * r, o2 = v2 * r;
    p[tid] = o0; p[tid + 256] = o1; p[tid + 512] = o2;
    pb[tid] = __float2bfloat16(o0);
    pb[tid + 256] = __float2bfloat16(o1);
    pb[tid + 512] = __float2bfloat16(o2);
}

// ---------------- residual + layernorm ----------------
__global__ void __launch_bounds__(256) ln_kernel(
    const float* __restrict__ hs, const float* __restrict__ lng,
    const float* __restrict__ lnb, float* __restrict__ out)
{
    __shared__ float sh1[8];
    __shared__ float sh2[8];
    const int row = blockIdx.x;
    const float* a  = g_att + (size_t)row * DIM;
    const float* x0 = hs    + (size_t)row * DIM;
    const int tid = threadIdx.x;

    float x[3];
    float s = 0.f, s2 = 0.f;
    #pragma unroll
    for (int j = 0; j < 3; ++j) {
        int c = tid + j * 256;
        x[j] = a[c] + x0[c];
        s += x[j];
        s2 = fmaf(x[j], x[j], s2);
    }
    s = warp_sum(s); s2 = warp_sum(s2);
    if ((tid & 31) == 0) { sh1[tid >> 5] = s; sh2[tid >> 5] = s2; }
    __syncthreads();
    float t1 = (tid & 31) < 8 ? sh1[tid & 31] : 0.f;
    float t2 = (tid & 31) < 8 ? sh2[tid & 31] : 0.f;
    s = warp_sum(t1); s2 = warp_sum(t2);

    const float mu = s * (1.0f / DIM);
    const float var = s2 * (1.0f / DIM) - mu * mu;
    const float rs = rsqrtf(var + LNEPS);
    #pragma unroll
    for (int j = 0; j < 3; ++j) {
        int c = tid + j * 256;
        out[(size_t)row * DIM + c] = (x[j] - mu) * rs * lng[c] + lnb[c];
    }
}

// ---------------- launcher ----------------
extern "C" void kernel_launch(void* const* d_in, const int* in_sizes, int n_in,
                              void* d_out, int out_size)
{
    const float* hs   = (const float*)d_in[0];
    const float* dist = (const float*)d_in[1];
    const float* ang  = (const float*)d_in[2];
    const float* mask = (const float*)d_in[3];
    const float* Wq   = (const float*)d_in[4];
    const float* bq   = (const float*)d_in[5];
    const float* Wk   = (const float*)d_in[6];
    const float* bk   = (const float*)d_in[7];
    const float* Wv   = (const float*)d_in[8];
    const float* bv   = (const float*)d_in[9];
    const float* Wd   = (const float*)d_in[10];
    const float* bd   = (const float*)d_in[11];
    const float* Wa   = (const float*)d_in[12];
    const float* ba   = (const float*)d_in[13];
    const float* Wo   = (const float*)d_in[14];
    const float* bo   = (const float*)d_in[15];
    const float* lng  = (const float*)d_in[16];
    const float* lnb  = (const float*)d_in[17];

    float* out   = (float*)d_out;
    float* probs = out + NOUT;

    // 1. operand prep (batched: z0=Aext, z1=Wq ext, z2=Wk ext, z3=Wv hi, z4=Wo hi)
    prep_all<<<dim3(NOUT/512, 5), 256>>>(hs, Wq, Wk, Wv, Wo);

    // 2. stage-1 GEMMs: Q proj, K proj (K=2304 split), Vt (b=0,1)
    gemm_stage1<<<dim3(DIM/128, ROWS/128, 4), 256>>>(bq, bk, bv);

    // 3. rank-1 coefficients + per-head Q/K splits
    qproj_kernel<<<(BH * SEQ) / 4, 128>>>(Wd, bd, Wa, ba);
    split_qk<<<dim3(2304, 2), 256>>>();

    // 4. scores (3-pass split per head, K=288) with fused bias/mask
    gemm_scores<<<dim3(SEQ/128, SEQ/128, BH), 256>>>(dist, ang, mask, probs);

    // 5. softmax (fp32 output + bf16 for ctx GEMM)
    softmax_kernel<<<BH * SEQ, 256>>>(probs);

    // 6. ctx = P @ V  (writes bf16 ctxh directly)
    gemm_ctx<<<dim3(1, SEQ/128, BH), 256>>>();

    // 7. out projection
    gemm_out<<<dim3(DIM/128, ROWS/128, 1), 256>>>(bo);

    // 8. residual + LN
    ln_kernel<<<ROWS, 256>>>(hs, lng, lnb, out);
}

// round 5
// speedup vs baseline: 2.4479x; 1.0375x over previous
#include <cuda_runtime.h>
#include <cuda_bf16.h>
#include <math.h>
#include <cstdint>

#define BATCH 2
#define SEQ   768
#define DIM   768
#define NH    8
#define HD    96
#define BH    (BATCH*NH)          // 16
#define ROWS  (BATCH*SEQ)         // 1536
#define NOUT  (BATCH*SEQ*DIM)     // 1179648
#define NPROB (BATCH*NH*SEQ*SEQ)  // 9437184
#define WSZ   (DIM*DIM)           // 589824
#define KEXT  (3*DIM)             // 2304
#define KS3   (3*HD)              // 288
#define LNEPS 1e-5f

// ---------------- device scratch ----------------
__device__ __align__(256) float g_Q[NOUT];
__device__ __align__(256) float g_K[NOUT];
__device__ __align__(256) float g_att[NOUT];
__device__ float g_cd[BH*SEQ];
__device__ float g_ca[BH*SEQ];
__device__ float g_c0[BH*SEQ];
__device__ __align__(256) __nv_bfloat16 g_Aext[ROWS*KEXT];     // [Ah|Al|Ah] of hs
__device__ __align__(256) __nv_bfloat16 g_Wext[2*DIM*KEXT];    // Wq,Wk [Bh|Bh|Bl]
__device__ __align__(256) __nv_bfloat16 g_Wvh[WSZ];
__device__ __align__(256) __nv_bfloat16 g_Woh[WSZ];
__device__ __align__(256) __nv_bfloat16 g_ctxh[NOUT];
__device__ __align__(256) __nv_bfloat16 g_Qs[BH*SEQ*KS3];      // per-head [h|l|h]
__device__ __align__(256) __nv_bfloat16 g_Ks[BH*SEQ*KS3];      // per-head [h|h|l]
__device__ __align__(256) __nv_bfloat16 g_Pb[NPROB];
__device__ __align__(256) __nv_bfloat16 g_Vt[BATCH*DIM*SEQ + 32*SEQ]; // [b][d][s], 32-row guard

// ---------------- mma helpers (baseline sm80+ ISA) ----------------
__device__ __forceinline__ uint32_t smem_u32(const void* p) {
    uint32_t a;
    asm("{ .reg .u64 t; cvta.to.shared.u64 t, %1; cvt.u32.u64 %0, t; }" : "=r"(a) : "l"(p));
    return a;
}
__device__ __forceinline__ void ldm4(uint32_t r[4], uint32_t a) {
    asm volatile("ldmatrix.sync.aligned.m8n8.x4.shared.b16 {%0,%1,%2,%3}, [%4];"
        : "=r"(r[0]), "=r"(r[1]), "=r"(r[2]), "=r"(r[3]) : "r"(a));
}
__device__ __forceinline__ void ldm2(uint32_t r[2], uint32_t a) {
    asm volatile("ldmatrix.sync.aligned.m8n8.x2.shared.b16 {%0,%1}, [%2];"
        : "=r"(r[0]), "=r"(r[1]) : "r"(a));
}
__device__ __forceinline__ void mma16816(float c[4], const uint32_t a[4], const uint32_t b[2]) {
    asm volatile("mma.sync.aligned.m16n8k16.row.col.f32.bf16.bf16.f32 "
        "{%0,%1,%2,%3}, {%4,%5,%6,%7}, {%8,%9}, {%0,%1,%2,%3};"
        : "+f"(c[0]), "+f"(c[1]), "+f"(c[2]), "+f"(c[3])
        : "r"(a[0]), "r"(a[1]), "r"(a[2]), "r"(a[3]), "r"(b[0]), "r"(b[1]));
}
__device__ __forceinline__ void cp16(uint32_t dst, const void* src) {
    asm volatile("cp.async.cg.shared.global [%0], [%1], 16;" :: "r"(dst), "l"(src) : "memory");
}
__device__ __forceinline__ void cp_commit() { asm volatile("cp.async.commit_group;" ::: "memory"); }
template<int N> __device__ __forceinline__ void cp_wait() {
    asm volatile("cp.async.wait_group %0;" :: "n"(N) : "memory");
}

#define SST 40                               // smem row stride (bf16)

// C[MTxNT] tile of A[M,K] * B[N,K]^T ; 8 warps (2m x 4n), warp tile (MT/2)x(NT/4).
template<int MT, int NT>
__device__ __forceinline__ void gemm_tile_t(
    const __nv_bfloat16* __restrict__ A, int lda,
    const __nv_bfloat16* __restrict__ B, int ldb,
    int m0, int n0, int K, float acc[MT/32][NT/32][4], char* smem)
{
    constexpr int FM = MT / 32, FN = NT / 32, WM = MT / 2, WN = NT / 4;
    __nv_bfloat16* As = (__nv_bfloat16*)smem;
    __nv_bfloat16* Bs = As + 2 * MT * SST;
    const int tid = threadIdx.x;
    const int wid = tid >> 5, lane = tid & 31;
    const int wm = wid >> 2, wn = wid & 3;
    const uint32_t sA = smem_u32(As), sB = smem_u32(Bs);

    const int row = tid >> 2;     // 0..63
    const int jj  = tid & 3;      // 16B chunk within 32-wide k

    const int nch = K / 32;

    {
        #pragma unroll
        for (int i = 0; i < MT / 64; ++i) {
            int r = row + i * 64;
            cp16(sA + (r * SST + jj * 8) * 2, A + (size_t)(m0 + r) * lda + jj * 8);
        }
        #pragma unroll
        for (int i = 0; i < NT / 64; ++i) {
            int r = row + i * 64;
            cp16(sB + (r * SST + jj * 8) * 2, B + (size_t)(n0 + r) * ldb + jj * 8);
        }
        cp_commit();
    }

    for (int c = 0; c < nch; ++c) {
        if (c + 1 < nch) {
            int k0 = (c + 1) * 32;
            uint32_t dA = sA + ((c + 1) & 1) * MT * SST * 2;
            uint32_t dB = sB + ((c + 1) & 1) * NT * SST * 2;
            #pragma unroll
            for (int i = 0; i < MT / 64; ++i) {
                int r = row + i * 64;
                cp16(dA + (r * SST + jj * 8) * 2, A + (size_t)(m0 + r) * lda + k0 + jj * 8);
            }
            #pragma unroll
            for (int i = 0; i < NT / 64; ++i) {
                int r = row + i * 64;
                cp16(dB + (r * SST + jj * 8) * 2, B + (size_t)(n0 + r) * ldb + k0 + jj * 8);
            }
            cp_commit();
            cp_wait<1>();
        } else {
            cp_wait<0>();
        }
        __syncthreads();

        uint32_t bA = sA + (c & 1) * MT * SST * 2;
        uint32_t bB = sB + (c & 1) * NT * SST * 2;
        #pragma unroll
        for (int ks = 0; ks < 2; ++ks) {
            const int k16 = ks * 16;
            uint32_t af[FM][4], bfr[FN][2];
            #pragma unroll
            for (int mf = 0; mf < FM; ++mf) {
                int baseRow = wm * WM + mf * 16;
                int mi = lane >> 3, r = lane & 7;
                int rr = baseRow + (mi & 1) * 8 + r;
                int cc = k16 + (mi >> 1) * 8;
                ldm4(af[mf], bA + (rr * SST + cc) * 2);
            }
            #pragma unroll
            for (int nf = 0; nf < FN; ++nf) {
                int baseRow = wn * WN + nf * 8;
                int r = lane & 7, mi = (lane >> 3) & 1;
                ldm2(bfr[nf], bB + ((baseRow + r) * SST + k16 + mi * 8) * 2);
            }
            #pragma unroll
            for (int mf = 0; mf < FM; ++mf)
                #pragma unroll
                for (int nf = 0; nf < FN; ++nf)
                    mma16816(acc[mf][nf], af[mf], bfr[nf]);
        }
        __syncthreads();
    }
}

#define SMEM_128 (2*2*128*SST*2)       // 40960
#define SMEM_64128 (2*(64+128)*SST*2)  // 30720

// ---------------- stage 1: Q-proj, K-proj (3-pass split) + Vt = Wv @ hs^T (bf16) ----------------
__global__ void __launch_bounds__(256) gemm_stage1(
    const float* __restrict__ bq, const float* __restrict__ bk,
    const float* __restrict__ bv)
{
    const int z = blockIdx.z;
    if (z >= 2 && blockIdx.y >= 6) return;   // Vt GEMM is M=768 (6 y-tiles)
    __shared__ __align__(16) char smem[SMEM_128];
    const int m0 = blockIdx.y << 7, n0 = blockIdx.x << 7;
    const int wid = threadIdx.x >> 5, lane = threadIdx.x & 31;
    const int wm = wid >> 2, wn = wid & 3;
    float acc[4][4][4] = {};

    if (z < 2) {
        const __nv_bfloat16* B = g_Wext + (size_t)z * DIM * KEXT;
        gemm_tile_t<128,128>(g_Aext, KEXT, B, KEXT, m0, n0, KEXT, acc, smem);
        const float* bias = z ? bk : bq;
        float* C = z ? g_K : g_Q;
        #pragma unroll
        for (int mf = 0; mf < 4; ++mf) {
            int r = m0 + wm * 64 + mf * 16 + (lane >> 2);
            #pragma unroll
            for (int nf = 0; nf < 4; ++nf) {
                int c = n0 + wn * 32 + nf * 8 + (lane & 3) * 2;
                float b0 = bias[c], b1 = bias[c + 1];
                float2 v0 = {acc[mf][nf][0] + b0, acc[mf][nf][1] + b1};
                float2 v1 = {acc[mf][nf][2] + b0, acc[mf][nf][3] + b1};
                *(float2*)(C + (size_t)r * DIM + c) = v0;
                *(float2*)(C + (size_t)(r + 8) * DIM + c) = v1;
            }
        }
    } else {
        const int b = z - 2;
        const __nv_bfloat16* B = g_Aext + (size_t)b * SEQ * KEXT;
        gemm_tile_t<128,128>(g_Wvh, DIM, B, KEXT, m0, n0, DIM, acc, smem);
        __nv_bfloat16* Vt = g_Vt + (size_t)b * DIM * SEQ;
        #pragma unroll
        for (int mf = 0; mf < 4; ++mf) {
            int r = m0 + wm * 64 + mf * 16 + (lane >> 2);
            float bv0 = bv[r], bv8 = bv[r + 8];
            #pragma unroll
            for (int nf = 0; nf < 4; ++nf) {
                int c = n0 + wn * 32 + nf * 8 + (lane & 3) * 2;
                __nv_bfloat162 h0, h1;
                h0.x = __float2bfloat16(acc[mf][nf][0] + bv0);
                h0.y = __float2bfloat16(acc[mf][nf][1] + bv0);
                h1.x = __float2bfloat16(acc[mf][nf][2] + bv8);
                h1.y = __float2bfloat16(acc[mf][nf][3] + bv8);
                *(__nv_bfloat162*)(Vt + (size_t)r * SEQ + c) = h0;
                *(__nv_bfloat162*)(Vt + (size_t)(r + 8) * SEQ + c) = h1;
            }
        }
    }
}

// ---------------- scores GEMM + fused bias/mask epilogue ----------------
__global__ void __launch_bounds__(256) gemm_scores(
    const float* __restrict__ dist, const float* __restrict__ ang,
    const float* __restrict__ mask, float* __restrict__ P)
{
    __shared__ __align__(16) char smem[SMEM_128];
    const int z = blockIdx.z, b = z >> 3;
    const __nv_bfloat16* A = g_Qs + (size_t)z * SEQ * KS3;
    const __nv_bfloat16* B = g_Ks + (size_t)z * SEQ * KS3;
    const int m0 = blockIdx.y << 7, n0 = blockIdx.x << 7;
    float acc[4][4][4] = {};
    gemm_tile_t<128,128>(A, KS3, B, KS3, m0, n0, KS3, acc, smem);

    const int wid = threadIdx.x >> 5, lane = threadIdx.x & 31;
    const int wm = wid >> 2, wn = wid & 3;
    const float inv = 0.1020620726159657f;  // 1/sqrt(96)

    // hoist mask bias per column pair (same for all rows)
    float mkb[4][2];
    #pragma unroll
    for (int nf = 0; nf < 4; ++nf) {
        int c = n0 + wn * 32 + nf * 8 + (lane & 3) * 2;
        float2 mk = *(const float2*)(mask + b * SEQ + c);
        mkb[nf][0] = (1.0f - mk.x) * -10000.0f;
        mkb[nf][1] = (1.0f - mk.y) * -10000.0f;
    }

    #pragma unroll
    for (int mf = 0; mf < 4; ++mf) {
        int r0 = m0 + wm * 64 + mf * 16 + (lane >> 2);
        #pragma unroll
        for (int half = 0; half < 2; ++half) {
            int r = r0 + half * 8;
            float cdv = g_cd[z * SEQ + r];
            float cav = g_ca[z * SEQ + r];
            float c0v = g_c0[z * SEQ + r];
            const float* drow = dist + ((size_t)b * SEQ + r) * SEQ;
            const float* arow = ang  + ((size_t)b * SEQ + r) * SEQ;
            float* prow = P + ((size_t)z * SEQ + r) * SEQ;
            #pragma unroll
            for (int nf = 0; nf < 4; ++nf) {
                int c = n0 + wn * 32 + nf * 8 + (lane & 3) * 2;
                float2 dv = *(const float2*)(drow + c);
                float2 av = *(const float2*)(arow + c);
                float s0 = acc[mf][nf][half * 2 + 0] * inv;
                float s1 = acc[mf][nf][half * 2 + 1] * inv;
                s0 = fmaf(dv.x, cdv, s0); s0 = fmaf(av.x, cav, s0);
                s1 = fmaf(dv.y, cdv, s1); s1 = fmaf(av.y, cav, s1);
                float2 o;
                o.x = s0 + c0v + mkb[nf][0];
                o.y = s1 + c0v + mkb[nf][1];
                *(float2*)(prow + c) = o;
            }
        }
    }
}

// ---------------- ctx = P @ V^T slice (64x128 tiles); writes bf16 ctxh ----------------
__global__ void __launch_bounds__(256) gemm_ctx()
{
    __shared__ __align__(16) char smem[SMEM_64128];
    const int z = blockIdx.z, b = z >> 3, h = z & 7;
    const __nv_bfloat16* A = g_Pb + (size_t)z * SEQ * SEQ;
    const __nv_bfloat16* B = g_Vt + (size_t)b * DIM * SEQ;
    const int m0 = blockIdx.y << 6;
    float acc[2][4][4] = {};
    gemm_tile_t<64,128>(A, SEQ, B, SEQ, m0, h * HD, SEQ, acc, smem);

    const int wid = threadIdx.x >> 5, lane = threadIdx.x & 31;
    const int wm = wid >> 2, wn = wid & 3;
    if (wn == 3) return;   // cols 96..127 cross into next head: discard
    #pragma unroll
    for (int mf = 0; mf < 2; ++mf) {
        int r = m0 + wm * 32 + mf * 16 + (lane >> 2);
        #pragma unroll
        for (int nf = 0; nf < 4; ++nf) {
            int c = wn * 32 + nf * 8 + (lane & 3) * 2;
            __nv_bfloat162 h0, h1;
            h0.x = __float2bfloat16(acc[mf][nf][0]);
            h0.y = __float2bfloat16(acc[mf][nf][1]);
            h1.x = __float2bfloat16(acc[mf][nf][2]);
            h1.y = __float2bfloat16(acc[mf][nf][3]);
            *(__nv_bfloat162*)(g_ctxh + ((size_t)b * SEQ + r) * DIM + h * HD + c) = h0;
            *(__nv_bfloat162*)(g_ctxh + ((size_t)b * SEQ + r + 8) * DIM + h * HD + c) = h1;
        }
    }
}

// ---------------- out projection (64x128 tiles): att = ctxh @ Woh^T + bo ----------------
__global__ void __launch_bounds__(256) gemm_out(const float* __restrict__ bo)
{
    __shared__ __align__(16) char smem[SMEM_64128];
    const int m0 = blockIdx.y << 6, n0 = blockIdx.x << 7;
    float acc[2][4][4] = {};
    gemm_tile_t<64,128>(g_ctxh, DIM, g_Woh, DIM, m0, n0, DIM, acc, smem);

    const int wid = threadIdx.x >> 5, lane = threadIdx.x & 31;
    const int wm = wid >> 2, wn = wid & 3;
    #pragma unroll
    for (int mf = 0; mf < 2; ++mf) {
        int r = m0 + wm * 32 + mf * 16 + (lane >> 2);
        #pragma unroll
        for (int nf = 0; nf < 4; ++nf) {
            int c = n0 + wn * 32 + nf * 8 + (lane & 3) * 2;
            float b0 = bo[c], b1 = bo[c + 1];
            float2 v0 = {acc[mf][nf][0] + b0, acc[mf][nf][1] + b1};
            float2 v1 = {acc[mf][nf][2] + b0, acc[mf][nf][3] + b1};
            *(float2*)(g_att + (size_t)r * DIM + c) = v0;
            *(float2*)(g_att + (size_t)(r + 8) * DIM + c) = v1;
        }
    }
}

// ---------------- batched operand prep ----------------
__global__ void __launch_bounds__(256) prep_all(
    const float* __restrict__ hs, const float* __restrict__ Wq,
    const float* __restrict__ Wk, const float* __restrict__ Wv,
    const float* __restrict__ Wo)
{
    const int z = blockIdx.y;
    const int idx = blockIdx.x * 256 + threadIdx.x;
    const int e = idx * 2;
    if (z == 0) {
        int r = e / DIM, c = e % DIM;
        float2 v = *(const float2*)(hs + e);
        __nv_bfloat162 h, l;
        h.x = __float2bfloat16(v.x); l.x = __float2bfloat16(v.x - __bfloat162float(h.x));
        h.y = __float2bfloat16(v.y); l.y = __float2bfloat16(v.y - __bfloat162float(h.y));
        __nv_bfloat16* row = g_Aext + (size_t)r * KEXT;
        *(__nv_bfloat162*)(row + c) = h;
        *(__nv_bfloat162*)(row + DIM + c) = l;
        *(__nv_bfloat162*)(row + 2 * DIM + c) = h;
        return;
    }
    if (e >= WSZ) return;
    if (z <= 2) {
        const float* w = (z == 1) ? Wq : Wk;
        int r = e / DIM, c = e % DIM;
        float2 v = *(const float2*)(w + e);
        __nv_bfloat162 h, l;
        h.x = __float2bfloat16(v.x); l.x = __float2bfloat16(v.x - __bfloat162float(h.x));
        h.y = __float2bfloat16(v.y); l.y = __float2bfloat16(v.y - __bfloat162float(h.y));
        __nv_bfloat16* row = g_Wext + (size_t)(z - 1) * DIM * KEXT + (size_t)r * KEXT;
        *(__nv_bfloat162*)(row + c) = h;
        *(__nv_bfloat162*)(row + DIM + c) = h;
        *(__nv_bfloat162*)(row + 2 * DIM + c) = l;
    } else {
        const float* w = (z == 3) ? Wv : Wo;
        __nv_bfloat16* y = (z == 3) ? g_Wvh : g_Woh;
        float2 v = *(const float2*)(w + e);
        __nv_bfloat162 hh;
        hh.x = __float2bfloat16(v.x); hh.y = __float2bfloat16(v.y);
        *(__nv_bfloat162*)(y + e) = hh;
    }
}

// ---------------- reductions ----------------
__device__ __forceinline__ float warp_sum(float v) {
    #pragma unroll
    for (int o = 16; o; o >>= 1) v += __shfl_xor_sync(0xffffffffu, v, o);
    return v;
}
__device__ __forceinline__ float warp_max(float v) {
    #pragma unroll
    for (int o = 16; o; o >>= 1) v = fmaxf(v, __shfl_xor_sync(0xffffffffu, v, o));
    return v;
}

// ---------------- fused: split Q/K to per-head slabs  +  rank-1 coefficients ----------------
__global__ void __launch_bounds__(256) qk_aux(
    const float* __restrict__ Wd, const float* __restrict__ bd,
    const float* __restrict__ Wa, const float* __restrict__ ba)
{
    const int role = blockIdx.y;
    if (role < 2) {
        const int isQ = (role == 0);
        const float* X = isQ ? g_Q : g_K;
        __nv_bfloat16* dst = isQ ? g_Qs : g_Ks;
        int idx = blockIdx.x * 256 + threadIdx.x;     // per 2 d's
        int d = (idx % 48) * 2;
        int h = (idx / 48) & 7;
        int s = (idx / 384) % SEQ;
        int b = idx / 294912;
        float2 v = *(const float2*)(X + ((size_t)b * SEQ + s) * DIM + h * HD + d);
        __nv_bfloat162 hi, lo;
        hi.x = __float2bfloat16(v.x); lo.x = __float2bfloat16(v.x - __bfloat162float(hi.x));
        hi.y = __float2bfloat16(v.y); lo.y = __float2bfloat16(v.y - __bfloat162float(hi.y));
        __nv_bfloat16* row = dst + ((size_t)(b * NH + h) * SEQ + s) * KS3;
        if (isQ) {
            *(__nv_bfloat162*)(row + d) = hi;
            *(__nv_bfloat162*)(row + HD + d) = lo;
            *(__nv_bfloat162*)(row + 2 * HD + d) = hi;
        } else {
            *(__nv_bfloat162*)(row + d) = hi;
            *(__nv_bfloat162*)(row + HD + d) = hi;
            *(__nv_bfloat162*)(row + 2 * HD + d) = lo;
        }
        return;
    }
    // role 2: rank-1 coefficients; 8 warps per block, need BH*SEQ=12288 warps -> 1536 blocks
    if (blockIdx.x >= 1536) return;
    int warp = blockIdx.x * 8 + (threadIdx.x >> 5);
    int lane = threadIdx.x & 31;
    int b = warp / (NH * SEQ);
    int h = (warp / SEQ) % NH;
    int i = warp % SEQ;
    const float* q = g_Q + ((size_t)b * SEQ + i) * DIM + h * HD;
    float sd = 0.f, sa = 0.f, s0 = 0.f;
    #pragma unroll
    for (int d = lane; d < HD; d += 32) {
        float qv = q[d];
        sd = fmaf(qv, Wd[d], sd);
        sa = fmaf(qv, Wa[d], sa);
        s0 = fmaf(qv, bd[d] + ba[d], s0);
    }
    sd = warp_sum(sd); sa = warp_sum(sa); s0 = warp_sum(s0);
    if (lane == 0) { g_cd[warp] = sd; g_ca[warp] = sa; g_c0[warp] = s0; }
}

// ---------------- softmax (fp32 in place + bf16 copy) ----------------
__global__ void __launch_bounds__(256) softmax_kernel(float* __restrict__ P)
{
    __shared__ float shm[8];
    __shared__ float shs[8];
    float* p = P + (size_t)blockIdx.x * SEQ;
    __nv_bfloat16* pb = g_Pb + (size_t)blockIdx.x * SEQ;
    const int tid = threadIdx.x;
    float v0 = p[tid], v1 = p[tid + 256], v2 = p[tid + 512];

    float mx = fmaxf(v0, fmaxf(v1, v2));
    mx = warp_max(mx);
    if ((tid & 31) == 0) shm[tid >> 5] = mx;
    __syncthreads();
    float t = (tid & 31) < 8 ? shm[tid & 31] : -1e30f;
    mx = warp_max(t);

    v0 = __expf(v0 - mx); v1 = __expf(v1 - mx); v2 = __expf(v2 - mx);
    float s = v0 + v1 + v2;
    s = warp_sum(s);
    if ((tid & 31) == 0) shs[tid >> 5] = s;
    __syncthreads();
    t = (tid & 31) < 8 ? shs[tid & 31] : 0.f;
    s = warp_sum(t);

    float r = 1.0f / s;
    float o0 = v0 * r, o1 = v1 * r, o2 = v2 * r;
    p[tid] = o0; p[tid + 256] = o1; p[tid + 512] = o2;
    pb[tid] = __float2bfloat16(o0);
    pb[tid + 256] = __float2bfloat16(o1);
    pb[tid + 512] = __float2bfloat16(o2);
}

// ---------------- residual + layernorm ----------------
__global__ void __launch_bounds__(256) ln_kernel(
    const float* __restrict__ hs, const float* __restrict__ lng,
    const float* __restrict__ lnb, float* __restrict__ out)
{
    __shared__ float sh1[8];
    __shared__ float sh2[8];
    const int row = blockIdx.x;
    const float* a  = g_att + (size_t)row * DIM;
    const float* x0 = hs    + (size_t)row * DIM;
    const int tid = threadIdx.x;

    float x[3];
    float s = 0.f, s2 = 0.f;
    #pragma unroll
    for (int j = 0; j < 3; ++j) {
        int c = tid + j * 256;
        x[j] = a[c] + x0[c];
        s += x[j];
        s2 = fmaf(x[j], x[j], s2);
    }
    s = warp_sum(s); s2 = warp_sum(s2);
    if ((tid & 31) == 0) { sh1[tid >> 5] = s; sh2[tid >> 5] = s2; }
    __syncthreads();
    float t1 = (tid & 31) < 8 ? sh1[tid & 31] : 0.f;
    float t2 = (tid & 31) < 8 ? sh2[tid & 31] : 0.f;
    s = warp_sum(t1); s2 = warp_sum(t2);

    const float mu = s * (1.0f / DIM);
    const float var = s2 * (1.0f / DIM) - mu * mu;
    const float rs = rsqrtf(var + LNEPS);
    #pragma unroll
    for (int j = 0; j < 3; ++j) {
        int c = tid + j * 256;
        out[(size_t)row * DIM + c] = (x[j] - mu) * rs * lng[c] + lnb[c];
    }
}

// ---------------- launcher ----------------
extern "C" void kernel_launch(void* const* d_in, const int* in_sizes, int n_in,
                              void* d_out, int out_size)
{
    const float* hs   = (const float*)d_in[0];
    const float* dist = (const float*)d_in[1];
    const float* ang  = (const float*)d_in[2];
    const float* mask = (const float*)d_in[3];
    const float* Wq   = (const float*)d_in[4];
    const float* bq   = (const float*)d_in[5];
    const float* Wk   = (const float*)d_in[6];
    const float* bk   = (const float*)d_in[7];
    const float* Wv   = (const float*)d_in[8];
    const float* bv   = (const float*)d_in[9];
    const float* Wd   = (const float*)d_in[10];
    const float* bd   = (const float*)d_in[11];
    const float* Wa   = (const float*)d_in[12];
    const float* ba   = (const float*)d_in[13];
    const float* Wo   = (const float*)d_in[14];
    const float* bo   = (const float*)d_in[15];
    const float* lng  = (const float*)d_in[16];
    const float* lnb  = (const float*)d_in[17];

    float* out   = (float*)d_out;
    float* probs = out + NOUT;

    // 1. operand prep (batched)
    prep_all<<<dim3(NOUT/512, 5), 256>>>(hs, Wq, Wk, Wv, Wo);

    // 2. stage-1 GEMMs: Q proj, K proj (K=2304 split), Vt (b=0,1)
    gemm_stage1<<<dim3(DIM/128, ROWS/128, 4), 256>>>(bq, bk, bv);

    // 3. fused Q/K per-head splits + rank-1 coefficients
    qk_aux<<<dim3(2304, 3), 256>>>(Wd, bd, Wa, ba);

    // 4. scores (3-pass split per head, K=288) with fused bias/mask
    gemm_scores<<<dim3(SEQ/128, SEQ/128, BH), 256>>>(dist, ang, mask, probs);

    // 5. softmax (fp32 output + bf16 for ctx GEMM)
    softmax_kernel<<<BH * SEQ, 256>>>(probs);

    // 6. ctx = P @ V (64x128 tiles, 192 CTAs)
    gemm_ctx<<<dim3(1, SEQ/64, BH), 256>>>();

    // 7. out projection (64x128 tiles, 144 CTAs)
    gemm_out<<<dim3(DIM/128, ROWS/64, 1), 256>>>(bo);

    // 8. residual + LN
    ln_kernel<<<ROWS, 256>>>(hs, lng, lnb, out);
}

// round 6
// speedup vs baseline: 2.5087x; 1.0248x over previous
#include <cuda_runtime.h>
#include <cuda_bf16.h>
#include <math.h>
#include <cstdint>

#define BATCH 2
#define SEQ   768
#define DIM   768
#define NH    8
#define HD    96
#define BH    (BATCH*NH)          // 16
#define ROWS  (BATCH*SEQ)         // 1536
#define NOUT  (BATCH*SEQ*DIM)     // 1179648
#define NPROB (BATCH*NH*SEQ*SEQ)  // 9437184
#define WSZ   (DIM*DIM)           // 589824
#define KEXT  (3*DIM)             // 2304
#define KS3   (3*HD)              // 288
#define LNEPS 1e-5f

// ---------------- device scratch ----------------
__device__ __align__(256) float g_Q[NOUT];
__device__ __align__(256) float g_K[NOUT];
__device__ __align__(256) float g_att[NOUT];
__device__ float g_cd[BH*SEQ];
__device__ float g_ca[BH*SEQ];
__device__ float g_c0[BH*SEQ];
__device__ __align__(256) __nv_bfloat16 g_Aext[ROWS*KEXT];     // [Ah|Al|Ah] of hs
__device__ __align__(256) __nv_bfloat16 g_Wext[2*DIM*KEXT];    // Wq,Wk [Bh|Bh|Bl]
__device__ __align__(256) __nv_bfloat16 g_Wvh[WSZ];
__device__ __align__(256) __nv_bfloat16 g_Woh[WSZ];
__device__ __align__(256) __nv_bfloat16 g_ctxh[NOUT];
__device__ __align__(256) __nv_bfloat16 g_Qs[BH*SEQ*KS3];      // per-head [h|l|h]
__device__ __align__(256) __nv_bfloat16 g_Ks[BH*SEQ*KS3];      // per-head [h|h|l]
__device__ __align__(256) __nv_bfloat16 g_Pb[NPROB];
__device__ __align__(256) __nv_bfloat16 g_Vt[BATCH*DIM*SEQ + 32*SEQ]; // [b][d][s], 32-row guard

// ---------------- mma helpers (baseline sm80+ ISA) ----------------
__device__ __forceinline__ uint32_t smem_u32(const void* p) {
    uint32_t a;
    asm("{ .reg .u64 t; cvta.to.shared.u64 t, %1; cvt.u32.u64 %0, t; }" : "=r"(a) : "l"(p));
    return a;
}
__device__ __forceinline__ void ldm4(uint32_t r[4], uint32_t a) {
    asm volatile("ldmatrix.sync.aligned.m8n8.x4.shared.b16 {%0,%1,%2,%3}, [%4];"
        : "=r"(r[0]), "=r"(r[1]), "=r"(r[2]), "=r"(r[3]) : "r"(a));
}
__device__ __forceinline__ void ldm2(uint32_t r[2], uint32_t a) {
    asm volatile("ldmatrix.sync.aligned.m8n8.x2.shared.b16 {%0,%1}, [%2];"
        : "=r"(r[0]), "=r"(r[1]) : "r"(a));
}
__device__ __forceinline__ void mma16816(float c[4], const uint32_t a[4], const uint32_t b[2]) {
    asm volatile("mma.sync.aligned.m16n8k16.row.col.f32.bf16.bf16.f32 "
        "{%0,%1,%2,%3}, {%4,%5,%6,%7}, {%8,%9}, {%0,%1,%2,%3};"
        : "+f"(c[0]), "+f"(c[1]), "+f"(c[2]), "+f"(c[3])
        : "r"(a[0]), "r"(a[1]), "r"(a[2]), "r"(a[3]), "r"(b[0]), "r"(b[1]));
}
__device__ __forceinline__ void cp16(uint32_t dst, const void* src) {
    asm volatile("cp.async.cg.shared.global [%0], [%1], 16;" :: "r"(dst), "l"(src) : "memory");
}
__device__ __forceinline__ void cp_commit() { asm volatile("cp.async.commit_group;" ::: "memory"); }
template<int N> __device__ __forceinline__ void cp_wait() {
    asm volatile("cp.async.wait_group %0;" :: "n"(N) : "memory");
}

#define SST 40                               // smem row stride (bf16)

// C[MTxNT] tile of A[M,K] * B[N,K]^T ; 8 warps (2m x 4n), warp tile (MT/2)x(NT/4).
// 3-stage cp.async pipeline, ONE __syncthreads per K-chunk.
template<int MT, int NT>
__device__ __forceinline__ void gemm_tile_t(
    const __nv_bfloat16* __restrict__ A, int lda,
    const __nv_bfloat16* __restrict__ B, int ldb,
    int m0, int n0, int K, float acc[MT/32][NT/32][4], char* smem)
{
    constexpr int FM = MT / 32, FN = NT / 32, WM = MT / 2, WN = NT / 4;
    constexpr int ABY = MT * SST * 2;
    constexpr int STGB = (MT + NT) * SST * 2;   // bytes per stage (A then B)
    const int tid = threadIdx.x;
    const int wid = tid >> 5, lane = tid & 31;
    const int wm = wid >> 2, wn = wid & 3;
    const uint32_t s0 = smem_u32(smem);

    const int row = tid >> 2;     // 0..63
    const int jj  = tid & 3;      // 16B chunk within 32-wide k
    const int nch = K / 32;

    // ---- stage loader ----
    auto loadStage = [&](int stage, int k0) {
        uint32_t dA = s0 + stage * STGB;
        uint32_t dB = dA + ABY;
        #pragma unroll
        for (int i = 0; i < MT / 64; ++i) {
            int r = row + i * 64;
            cp16(dA + (r * SST + jj * 8) * 2, A + (size_t)(m0 + r) * lda + k0 + jj * 8);
        }
        #pragma unroll
        for (int i = 0; i < NT / 64; ++i) {
            int r = row + i * 64;
            cp16(dB + (r * SST + jj * 8) * 2, B + (size_t)(n0 + r) * ldb + k0 + jj * 8);
        }
        cp_commit();
    };

    loadStage(0, 0);
    if (nch > 1) loadStage(1, 32);

    int stage = 0;
    for (int c = 0; c < nch; ++c) {
        if (c + 1 < nch) cp_wait<1>(); else cp_wait<0>();
        __syncthreads();
        if (c + 2 < nch) {
            int ns = stage + 2; if (ns >= 3) ns -= 3;
            loadStage(ns, (c + 2) * 32);
        }

        uint32_t bA = s0 + stage * STGB;
        uint32_t bB = bA + ABY;
        #pragma unroll
        for (int ks = 0; ks < 2; ++ks) {
            const int k16 = ks * 16;
            uint32_t af[FM][4], bfr[FN][2];
            #pragma unroll
            for (int mf = 0; mf < FM; ++mf) {
                int baseRow = wm * WM + mf * 16;
                int mi = lane >> 3, r = lane & 7;
                int rr = baseRow + (mi & 1) * 8 + r;
                int cc = k16 + (mi >> 1) * 8;
                ldm4(af[mf], bA + (rr * SST + cc) * 2);
            }
            #pragma unroll
            for (int nf = 0; nf < FN; ++nf) {
                int baseRow = wn * WN + nf * 8;
                int r = lane & 7, mi = (lane >> 3) & 1;
                ldm2(bfr[nf], bB + ((baseRow + r) * SST + k16 + mi * 8) * 2);
            }
            #pragma unroll
            for (int mf = 0; mf < FM; ++mf)
                #pragma unroll
                for (int nf = 0; nf < FN; ++nf)
                    mma16816(acc[mf][nf], af[mf], bfr[nf]);
        }
        if (++stage == 3) stage = 0;
    }
    __syncthreads();
}

#define SMEM3_128   (3*(128+128)*SST*2)   // 61440
#define SMEM3_64128 (3*(64+128)*SST*2)    // 46080

// ---------------- stage 1: Q-proj, K-proj (3-pass split) + Vt = Wv @ hs^T (bf16) ----------------
__global__ void __launch_bounds__(256) gemm_stage1(
    const float* __restrict__ bq, const float* __restrict__ bk,
    const float* __restrict__ bv)
{
    const int z = blockIdx.z;
    if (z >= 2 && blockIdx.y >= 6) return;   // Vt GEMM is M=768 (6 y-tiles)
    extern __shared__ __align__(16) char smem[];
    const int m0 = blockIdx.y << 7, n0 = blockIdx.x << 7;
    const int wid = threadIdx.x >> 5, lane = threadIdx.x & 31;
    const int wm = wid >> 2, wn = wid & 3;
    float acc[4][4][4] = {};

    if (z < 2) {
        const __nv_bfloat16* B = g_Wext + (size_t)z * DIM * KEXT;
        gemm_tile_t<128,128>(g_Aext, KEXT, B, KEXT, m0, n0, KEXT, acc, smem);
        const float* bias = z ? bk : bq;
        float* C = z ? g_K : g_Q;
        #pragma unroll
        for (int mf = 0; mf < 4; ++mf) {
            int r = m0 + wm * 64 + mf * 16 + (lane >> 2);
            #pragma unroll
            for (int nf = 0; nf < 4; ++nf) {
                int c = n0 + wn * 32 + nf * 8 + (lane & 3) * 2;
                float b0 = bias[c], b1 = bias[c + 1];
                float2 v0 = {acc[mf][nf][0] + b0, acc[mf][nf][1] + b1};
                float2 v1 = {acc[mf][nf][2] + b0, acc[mf][nf][3] + b1};
                *(float2*)(C + (size_t)r * DIM + c) = v0;
                *(float2*)(C + (size_t)(r + 8) * DIM + c) = v1;
            }
        }
    } else {
        const int b = z - 2;
        const __nv_bfloat16* B = g_Aext + (size_t)b * SEQ * KEXT;
        gemm_tile_t<128,128>(g_Wvh, DIM, B, KEXT, m0, n0, DIM, acc, smem);
        __nv_bfloat16* Vt = g_Vt + (size_t)b * DIM * SEQ;
        #pragma unroll
        for (int mf = 0; mf < 4; ++mf) {
            int r = m0 + wm * 64 + mf * 16 + (lane >> 2);
            float bv0 = bv[r], bv8 = bv[r + 8];
            #pragma unroll
            for (int nf = 0; nf < 4; ++nf) {
                int c = n0 + wn * 32 + nf * 8 + (lane & 3) * 2;
                __nv_bfloat162 h0, h1;
                h0.x = __float2bfloat16(acc[mf][nf][0] + bv0);
                h0.y = __float2bfloat16(acc[mf][nf][1] + bv0);
                h1.x = __float2bfloat16(acc[mf][nf][2] + bv8);
                h1.y = __float2bfloat16(acc[mf][nf][3] + bv8);
                *(__nv_bfloat162*)(Vt + (size_t)r * SEQ + c) = h0;
                *(__nv_bfloat162*)(Vt + (size_t)(r + 8) * SEQ + c) = h1;
            }
        }
    }
}

// ---------------- scores GEMM + fused bias/mask epilogue ----------------
__global__ void __launch_bounds__(256) gemm_scores(
    const float* __restrict__ dist, const float* __restrict__ ang,
    const float* __restrict__ mask, float* __restrict__ P)
{
    extern __shared__ __align__(16) char smem[];
    const int z = blockIdx.z, b = z >> 3;
    const __nv_bfloat16* A = g_Qs + (size_t)z * SEQ * KS3;
    const __nv_bfloat16* B = g_Ks + (size_t)z * SEQ * KS3;
    const int m0 = blockIdx.y << 7, n0 = blockIdx.x << 7;
    float acc[4][4][4] = {};
    gemm_tile_t<128,128>(A, KS3, B, KS3, m0, n0, KS3, acc, smem);

    const int wid = threadIdx.x >> 5, lane = threadIdx.x & 31;
    const int wm = wid >> 2, wn = wid & 3;
    const float inv = 0.1020620726159657f;  // 1/sqrt(96)

    float mkb[4][2];
    #pragma unroll
    for (int nf = 0; nf < 4; ++nf) {
        int c = n0 + wn * 32 + nf * 8 + (lane & 3) * 2;
        float2 mk = *(const float2*)(mask + b * SEQ + c);
        mkb[nf][0] = (1.0f - mk.x) * -10000.0f;
        mkb[nf][1] = (1.0f - mk.y) * -10000.0f;
    }

    #pragma unroll
    for (int mf = 0; mf < 4; ++mf) {
        int r0 = m0 + wm * 64 + mf * 16 + (lane >> 2);
        #pragma unroll
        for (int half = 0; half < 2; ++half) {
            int r = r0 + half * 8;
            float cdv = g_cd[z * SEQ + r];
            float cav = g_ca[z * SEQ + r];
            float c0v = g_c0[z * SEQ + r];
            const float* drow = dist + ((size_t)b * SEQ + r) * SEQ;
            const float* arow = ang  + ((size_t)b * SEQ + r) * SEQ;
            float* prow = P + ((size_t)z * SEQ + r) * SEQ;
            #pragma unroll
            for (int nf = 0; nf < 4; ++nf) {
                int c = n0 + wn * 32 + nf * 8 + (lane & 3) * 2;
                float2 dv = *(const float2*)(drow + c);
                float2 av = *(const float2*)(arow + c);
                float s0 = acc[mf][nf][half * 2 + 0] * inv;
                float s1 = acc[mf][nf][half * 2 + 1] * inv;
                s0 = fmaf(dv.x, cdv, s0); s0 = fmaf(av.x, cav, s0);
                s1 = fmaf(dv.y, cdv, s1); s1 = fmaf(av.y, cav, s1);
                float2 o;
                o.x = s0 + c0v + mkb[nf][0];
                o.y = s1 + c0v + mkb[nf][1];
                *(float2*)(prow + c) = o;
            }
        }
    }
}

// ---------------- ctx = P @ V^T slice (64x128 tiles); writes bf16 ctxh ----------------
__global__ void __launch_bounds__(256) gemm_ctx()
{
    extern __shared__ __align__(16) char smem[];
    const int z = blockIdx.z, b = z >> 3, h = z & 7;
    const __nv_bfloat16* A = g_Pb + (size_t)z * SEQ * SEQ;
    const __nv_bfloat16* B = g_Vt + (size_t)b * DIM * SEQ;
    const int m0 = blockIdx.y << 6;
    float acc[2][4][4] = {};
    gemm_tile_t<64,128>(A, SEQ, B, SEQ, m0, h * HD, SEQ, acc, smem);

    const int wid = threadIdx.x >> 5, lane = threadIdx.x & 31;
    const int wm = wid >> 2, wn = wid & 3;
    if (wn == 3) return;   // cols 96..127 cross into next head: discard
    #pragma unroll
    for (int mf = 0; mf < 2; ++mf) {
        int r = m0 + wm * 32 + mf * 16 + (lane >> 2);
        #pragma unroll
        for (int nf = 0; nf < 4; ++nf) {
            int c = wn * 32 + nf * 8 + (lane & 3) * 2;
            __nv_bfloat162 h0, h1;
            h0.x = __float2bfloat16(acc[mf][nf][0]);
            h0.y = __float2bfloat16(acc[mf][nf][1]);
            h1.x = __float2bfloat16(acc[mf][nf][2]);
            h1.y = __float2bfloat16(acc[mf][nf][3]);
            *(__nv_bfloat162*)(g_ctxh + ((size_t)b * SEQ + r) * DIM + h * HD + c) = h0;
            *(__nv_bfloat162*)(g_ctxh + ((size_t)b * SEQ + r + 8) * DIM + h * HD + c) = h1;
        }
    }
}

// ---------------- out projection (64x128 tiles): att = ctxh @ Woh^T + bo ----------------
__global__ void __launch_bounds__(256) gemm_out(const float* __restrict__ bo)
{
    extern __shared__ __align__(16) char smem[];
    const int m0 = blockIdx.y << 6, n0 = blockIdx.x << 7;
    float acc[2][4][4] = {};
    gemm_tile_t<64,128>(g_ctxh, DIM, g_Woh, DIM, m0, n0, DIM, acc, smem);

    const int wid = threadIdx.x >> 5, lane = threadIdx.x & 31;
    const int wm = wid >> 2, wn = wid & 3;
    #pragma unroll
    for (int mf = 0; mf < 2; ++mf) {
        int r = m0 + wm * 32 + mf * 16 + (lane >> 2);
        #pragma unroll
        for (int nf = 0; nf < 4; ++nf) {
            int c = n0 + wn * 32 + nf * 8 + (lane & 3) * 2;
            float b0 = bo[c], b1 = bo[c + 1];
            float2 v0 = {acc[mf][nf][0] + b0, acc[mf][nf][1] + b1};
            float2 v1 = {acc[mf][nf][2] + b0, acc[mf][nf][3] + b1};
            *(float2*)(g_att + (size_t)r * DIM + c) = v0;
            *(float2*)(g_att + (size_t)(r + 8) * DIM + c) = v1;
        }
    }
}

// ---------------- batched operand prep ----------------
__global__ void __launch_bounds__(256) prep_all(
    const float* __restrict__ hs, const float* __restrict__ Wq,
    const float* __restrict__ Wk, const float* __restrict__ Wv,
    const float* __restrict__ Wo)
{
    const int z = blockIdx.y;
    const int idx = blockIdx.x * 256 + threadIdx.x;
    const int e = idx * 2;
    if (z == 0) {
        int r = e / DIM, c = e % DIM;
        float2 v = *(const float2*)(hs + e);
        __nv_bfloat162 h, l;
        h.x = __float2bfloat16(v.x); l.x = __float2bfloat16(v.x - __bfloat162float(h.x));
        h.y = __float2bfloat16(v.y); l.y = __float2bfloat16(v.y - __bfloat162float(h.y));
        __nv_bfloat16* row = g_Aext + (size_t)r * KEXT;
        *(__nv_bfloat162*)(row + c) = h;
        *(__nv_bfloat162*)(row + DIM + c) = l;
        *(__nv_bfloat162*)(row + 2 * DIM + c) = h;
        return;
    }
    if (e >= WSZ) return;
    if (z <= 2) {
        const float* w = (z == 1) ? Wq : Wk;
        int r = e / DIM, c = e % DIM;
        float2 v = *(const float2*)(w + e);
        __nv_bfloat162 h, l;
        h.x = __float2bfloat16(v.x); l.x = __float2bfloat16(v.x - __bfloat162float(h.x));
        h.y = __float2bfloat16(v.y); l.y = __float2bfloat16(v.y - __bfloat162float(h.y));
        __nv_bfloat16* row = g_Wext + (size_t)(z - 1) * DIM * KEXT + (size_t)r * KEXT;
        *(__nv_bfloat162*)(row + c) = h;
        *(__nv_bfloat162*)(row + DIM + c) = h;
        *(__nv_bfloat162*)(row + 2 * DIM + c) = l;
    } else {
        const float* w = (z == 3) ? Wv : Wo;
        __nv_bfloat16* y = (z == 3) ? g_Wvh : g_Woh;
        float2 v = *(const float2*)(w + e);
        __nv_bfloat162 hh;
        hh.x = __float2bfloat16(v.x); hh.y = __float2bfloat16(v.y);
        *(__nv_bfloat162*)(y + e) = hh;
    }
}

// ---------------- reductions ----------------
__device__ __forceinline__ float warp_sum(float v) {
    #pragma unroll
    for (int o = 16; o; o >>= 1) v += __shfl_xor_sync(0xffffffffu, v, o);
    return v;
}
__device__ __forceinline__ float warp_max(float v) {
    #pragma unroll
    for (int o = 16; o; o >>= 1) v = fmaxf(v, __shfl_xor_sync(0xffffffffu, v, o));
    return v;
}

// ---------------- fused: split Q/K to per-head slabs  +  rank-1 coefficients ----------------
__global__ void __launch_bounds__(256) qk_aux(
    const float* __restrict__ Wd, const float* __restrict__ bd,
    const float* __restrict__ Wa, const float* __restrict__ ba)
{
    const int role = blockIdx.y;
    if (role < 2) {
        const int isQ = (role == 0);
        const float* X = isQ ? g_Q : g_K;
        __nv_bfloat16* dst = isQ ? g_Qs : g_Ks;
        int idx = blockIdx.x * 256 + threadIdx.x;     // per 2 d's
        int d = (idx % 48) * 2;
        int h = (idx / 48) & 7;
        int s = (idx / 384) % SEQ;
        int b = idx / 294912;
        float2 v = *(const float2*)(X + ((size_t)b * SEQ + s) * DIM + h * HD + d);
        __nv_bfloat162 hi, lo;
        hi.x = __float2bfloat16(v.x); lo.x = __float2bfloat16(v.x - __bfloat162float(hi.x));
        hi.y = __float2bfloat16(v.y); lo.y = __float2bfloat16(v.y - __bfloat162float(hi.y));
        __nv_bfloat16* row = dst + ((size_t)(b * NH + h) * SEQ + s) * KS3;
        if (isQ) {
            *(__nv_bfloat162*)(row + d) = hi;
            *(__nv_bfloat162*)(row + HD + d) = lo;
            *(__nv_bfloat162*)(row + 2 * HD + d) = hi;
        } else {
            *(__nv_bfloat162*)(row + d) = hi;
            *(__nv_bfloat162*)(row + HD + d) = hi;
            *(__nv_bfloat162*)(row + 2 * HD + d) = lo;
        }
        return;
    }
    if (blockIdx.x >= 1536) return;
    int warp = blockIdx.x * 8 + (threadIdx.x >> 5);
    int lane = threadIdx.x & 31;
    int b = warp / (NH * SEQ);
    int h = (warp / SEQ) % NH;
    int i = warp % SEQ;
    const float* q = g_Q + ((size_t)b * SEQ + i) * DIM + h * HD;
    float sd = 0.f, sa = 0.f, s0 = 0.f;
    #pragma unroll
    for (int d = lane; d < HD; d += 32) {
        float qv = q[d];
        sd = fmaf(qv, Wd[d], sd);
        sa = fmaf(qv, Wa[d], sa);
        s0 = fmaf(qv, bd[d] + ba[d], s0);
    }
    sd = warp_sum(sd); sa = warp_sum(sa); s0 = warp_sum(s0);
    if (lane == 0) { g_cd[warp] = sd; g_ca[warp] = sa; g_c0[warp] = s0; }
}

// ---------------- softmax (fp32 in place + bf16 copy) ----------------
__global__ void __launch_bounds__(256) softmax_kernel(float* __restrict__ P)
{
    __shared__ float shm[8];
    __shared__ float shs[8];
    float* p = P + (size_t)blockIdx.x * SEQ;
    __nv_bfloat16* pb = g_Pb + (size_t)blockIdx.x * SEQ;
    const int tid = threadIdx.x;
    float v0 = p[tid], v1 = p[tid + 256], v2 = p[tid + 512];

    float mx = fmaxf(v0, fmaxf(v1, v2));
    mx = warp_max(mx);
    if ((tid & 31) == 0) shm[tid >> 5] = mx;
    __syncthreads();
    float t = (tid & 31) < 8 ? shm[tid & 31] : -1e30f;
    mx = warp_max(t);

    v0 = __expf(v0 - mx); v1 = __expf(v1 - mx); v2 = __expf(v2 - mx);
    float s = v0 + v1 + v2;
    s = warp_sum(s);
    if ((tid & 31) == 0) shs[tid >> 5] = s;
    __syncthreads();
    t = (tid & 31) < 8 ? shs[tid & 31] : 0.f;
    s = warp_sum(t);

    float r = 1.0f / s;
    float o0 = v0 * r, o1 = v1 * r, o2 = v2 * r;
    p[tid] = o0; p[tid + 256] = o1; p[tid + 512] = o2;
    pb[tid] = __float2bfloat16(o0);
    pb[tid + 256] = __float2bfloat16(o1);
    pb[tid + 512] = __float2bfloat16(o2);
}

// ---------------- residual + layernorm ----------------
__global__ void __launch_bounds__(256) ln_kernel(
    const float* __restrict__ hs, const float* __restrict__ lng,
    const float* __restrict__ lnb, float* __restrict__ out)
{
    __shared__ float sh1[8];
    __shared__ float sh2[8];
    const int row = blockIdx.x;
    const float* a  = g_att + (size_t)row * DIM;
    const float* x0 = hs    + (size_t)row * DIM;
    const int tid = threadIdx.x;

    float x[3];
    float s = 0.f, s2 = 0.f;
    #pragma unroll
    for (int j = 0; j < 3; ++j) {
        int c = tid + j * 256;
        x[j] = a[c] + x0[c];
        s += x[j];
        s2 = fmaf(x[j], x[j], s2);
    }
    s = warp_sum(s); s2 = warp_sum(s2);
    if ((tid & 31) == 0) { sh1[tid >> 5] = s; sh2[tid >> 5] = s2; }
    __syncthreads();
    float t1 = (tid & 31) < 8 ? sh1[tid & 31] : 0.f;
    float t2 = (tid & 31) < 8 ? sh2[tid & 31] : 0.f;
    s = warp_sum(t1); s2 = warp_sum(t2);

    const float mu = s * (1.0f / DIM);
    const float var = s2 * (1.0f / DIM) - mu * mu;
    const float rs = rsqrtf(var + LNEPS);
    #pragma unroll
    for (int j = 0; j < 3; ++j) {
        int c = tid + j * 256;
        out[(size_t)row * DIM + c] = (x[j] - mu) * rs * lng[c] + lnb[c];
    }
}

// ---------------- launcher ----------------
extern "C" void kernel_launch(void* const* d_in, const int* in_sizes, int n_in,
                              void* d_out, int out_size)
{
    const float* hs   = (const float*)d_in[0];
    const float* dist = (const float*)d_in[1];
    const float* ang  = (const float*)d_in[2];
    const float* mask = (const float*)d_in[3];
    const float* Wq   = (const float*)d_in[4];
    const float* bq   = (const float*)d_in[5];
    const float* Wk   = (const float*)d_in[6];
    const float* bk   = (const float*)d_in[7];
    const float* Wv   = (const float*)d_in[8];
    const float* bv   = (const float*)d_in[9];
    const float* Wd   = (const float*)d_in[10];
    const float* bd   = (const float*)d_in[11];
    const float* Wa   = (const float*)d_in[12];
    const float* ba   = (const float*)d_in[13];
    const float* Wo   = (const float*)d_in[14];
    const float* bo   = (const float*)d_in[15];
    const float* lng  = (const float*)d_in[16];
    const float* lnb  = (const float*)d_in[17];

    float* out   = (float*)d_out;
    float* probs = out + NOUT;

    static bool attr_done = false;
    if (!attr_done) {
        cudaFuncSetAttribute(gemm_stage1, cudaFuncAttributeMaxDynamicSharedMemorySize, SMEM3_128);
        cudaFuncSetAttribute(gemm_scores, cudaFuncAttributeMaxDynamicSharedMemorySize, SMEM3_128);
        cudaFuncSetAttribute(gemm_ctx,    cudaFuncAttributeMaxDynamicSharedMemorySize, SMEM3_64128);
        cudaFuncSetAttribute(gemm_out,    cudaFuncAttributeMaxDynamicSharedMemorySize, SMEM3_64128);
        attr_done = true;
    }

    // 1. operand prep (batched)
    prep_all<<<dim3(NOUT/512, 5), 256>>>(hs, Wq, Wk, Wv, Wo);

    // 2. stage-1 GEMMs: Q proj, K proj (K=2304 split), Vt (b=0,1)
    gemm_stage1<<<dim3(DIM/128, ROWS/128, 4), 256, SMEM3_128>>>(bq, bk, bv);

    // 3. fused Q/K per-head splits + rank-1 coefficients
    qk_aux<<<dim3(2304, 3), 256>>>(Wd, bd, Wa, ba);

    // 4. scores (3-pass split per head, K=288) with fused bias/mask
    gemm_scores<<<dim3(SEQ/128, SEQ/128, BH), 256, SMEM3_128>>>(dist, ang, mask, probs);

    // 5. softmax (fp32 output + bf16 for ctx GEMM)
    softmax_kernel<<<BH * SEQ, 256>>>(probs);

    // 6. ctx = P @ V (64x128 tiles, 192 CTAs)
    gemm_ctx<<<dim3(1, SEQ/64, BH), 256, SMEM3_64128>>>();

    // 7. out projection (64x128 tiles, 144 CTAs)
    gemm_out<<<dim3(DIM/128, ROWS/64, 1), 256, SMEM3_64128>>>(bo);

    // 8. residual + LN
    ln_kernel<<<ROWS, 256>>>(hs, lng, lnb, out);
}